// round 13
// baseline (speedup 1.0000x reference)
#include <cuda_runtime.h>
#include <cuda_bf16.h>
#include <math.h>
#include <stdint.h>

#define BB   16
#define SL   2048
#define DD   128
#define HH   4
#define NLAY 4
#define DKH  32
#define DFF  256
#define NF   129
#define DMG  16
#define INTD 11
#define NTOK (BB*SL)
#define FMIN_F (-3.402823466e38f)

// per-layer transposed bf16 weight planes: qkv[384x128] | wo[128x128] | w1[256x128] | w2[128x256]
#define WT_LAYER 131072
#define WT_QKV   0
#define WT_WO    49152
#define WT_W1    65536
#define WT_W2    98304
#define WF_OFF   (NLAY*WT_LAYER)
#define WT_TOTAL (WF_OFF + DD*DD)

// ---------------- scratch (device globals: allocation-free) ----------------
__device__ float g_x[NTOK*DD];          // fp32 residual stream (pool needs it)
__device__ float g_ff[NTOK*DD];         // fusion tanh output (fp32)
__device__ float g_demo[BB*DD];
__device__ float g_att[BB*SL];
__device__ float g_ts[BB*DD];
__device__ __nv_bfloat16 g_wt0[WT_TOTAL];
__device__ __nv_bfloat16 g_wt1[WT_TOTAL];
__device__ __nv_bfloat16 g_wt2[WT_TOTAL];
// canonical split planes
__device__ __nv_bfloat16 g_x0[NTOK*DD], g_x1[NTOK*DD], g_x2[NTOK*DD];     // activations
__device__ __nv_bfloat16 g_f0[NTOK*DFF], g_f1[NTOK*DFF], g_f2[NTOK*DFF];  // FFN hidden
__device__ __nv_bfloat16 g_o0[NTOK*DD], g_o1[NTOK*DD], g_o2[NTOK*DD];     // attn out
// per-(b,h) planes of Q (3), K (3), V (2): [((b*4+h)*SL + j)*32 + e]
#define PL_ELEMS (BB*HH*SL*DKH)
__device__ __nv_bfloat16 g_q0[PL_ELEMS], g_q1[PL_ELEMS], g_q2[PL_ELEMS];
__device__ __nv_bfloat16 g_k0[PL_ELEMS], g_k1[PL_ELEMS], g_k2[PL_ELEMS];
__device__ __nv_bfloat16 g_v0[PL_ELEMS], g_v1[PL_ELEMS];
__device__ unsigned char g_mask[NTOK];
__device__ int g_idx[NTOK];
__device__ int g_nb[BB];
__device__ int g_npad[BB];
__device__ int g_cnt[2];

// ---------------- PTX helpers -------------------------------------------------
__device__ __forceinline__ uint32_t smem_u32(const void* p) {
    uint32_t a;
    asm("{ .reg .u64 t; cvta.to.shared.u64 t, %1; cvt.u32.u64 %0, t; }" : "=r"(a) : "l"(p));
    return a;
}
__device__ __forceinline__ void ldsm4(uint32_t* r, uint32_t addr) {
    asm volatile("ldmatrix.sync.aligned.m8n8.x4.shared.b16 {%0,%1,%2,%3}, [%4];"
        : "=r"(r[0]), "=r"(r[1]), "=r"(r[2]), "=r"(r[3]) : "r"(addr));
}
__device__ __forceinline__ void ldsm4t(uint32_t* r, uint32_t addr) {
    asm volatile("ldmatrix.sync.aligned.m8n8.x4.trans.shared.b16 {%0,%1,%2,%3}, [%4];"
        : "=r"(r[0]), "=r"(r[1]), "=r"(r[2]), "=r"(r[3]) : "r"(addr));
}
__device__ __forceinline__ void mma16816(float* d, const uint32_t* a, const uint32_t* b) {
    asm volatile("mma.sync.aligned.m16n8k16.row.col.f32.bf16.bf16.f32 "
        "{%0,%1,%2,%3}, {%4,%5,%6,%7}, {%8,%9}, {%0,%1,%2,%3};"
        : "+f"(d[0]), "+f"(d[1]), "+f"(d[2]), "+f"(d[3])
        : "r"(a[0]), "r"(a[1]), "r"(a[2]), "r"(a[3]), "r"(b[0]), "r"(b[1]));
}
__device__ __forceinline__ void split3(float x, uint16_t& h0, uint16_t& h1, uint16_t& h2) {
    __nv_bfloat16 b0 = __float2bfloat16(x);
    float r1 = x - __bfloat162float(b0);
    __nv_bfloat16 b1 = __float2bfloat16(r1);
    float r2 = r1 - __bfloat162float(b1);
    __nv_bfloat16 b2 = __float2bfloat16(r2);
    h0 = __bfloat16_as_ushort(b0);
    h1 = __bfloat16_as_ushort(b1);
    h2 = __bfloat16_as_ushort(b2);
}
__device__ __forceinline__ void split2(float x, uint16_t& h0, uint16_t& h1) {
    __nv_bfloat16 b0 = __float2bfloat16(x);
    float r1 = x - __bfloat162float(b0);
    __nv_bfloat16 b1 = __float2bfloat16(r1);
    h0 = __bfloat16_as_ushort(b0);
    h1 = __bfloat16_as_ushort(b1);
}
__device__ __forceinline__ uint32_t pack16(uint16_t lo, uint16_t hi) {
    return (uint32_t)lo | ((uint32_t)hi << 16);
}

// ---------------- mask dtype detection + normalization ----------------------
__global__ void mask_reset_kernel() {
    if (threadIdx.x < 2) g_cnt[threadIdx.x] = 0;
}
__global__ void mask_scan_kernel(const unsigned int* __restrict__ w) {
    int i = blockIdx.x*256 + threadIdx.x;
    unsigned int v = w[i];
    if (v > 1u) atomicOr(&g_cnt[0], 1);
    if (v != 0u && v != 0x3F800000u) atomicOr(&g_cnt[1], 1);
}
__global__ void mask_convert_kernel(const void* __restrict__ p) {
    int i = blockIdx.x*256 + threadIdx.x;
    unsigned char m;
    if (g_cnt[0] == 0)       m = (unsigned char)(((const int*)p)[i] != 0);
    else if (g_cnt[1] == 0)  m = (unsigned char)(((const float*)p)[i] != 0.0f);
    else                     m = (unsigned char)(((const unsigned char*)p)[i] != 0);
    g_mask[i] = m;
}

// ---------------- stable compaction ------------------------------------------
__global__ void compact_kernel()
{
    int b = blockIdx.x, tid = threadIdx.x;
    __shared__ int sc[256];
    __shared__ int sbase;
    if (tid == 0) sbase = 0;
    __syncthreads();
    for (int c = 0; c < SL; c += 256) {
        int l = c + tid;
        int m = g_mask[b*SL + l];
        sc[tid] = m;
        __syncthreads();
#pragma unroll
        for (int s = 1; s < 256; s <<= 1) {
            int v = (tid >= s) ? sc[tid - s] : 0;
            __syncthreads();
            sc[tid] += v;
            __syncthreads();
        }
        int pos = sbase + sc[tid] - m;
        if (m) g_idx[b*SL + pos] = l;
        int tot = sc[255];
        __syncthreads();
        if (tid == 0) sbase += tot;
        __syncthreads();
    }
    if (tid == 0) { g_nb[b] = sbase; g_npad[b] = (sbase + 127) & ~127; }
}

// ---------------- embedding (compacted): fp32 x + x planes -------------------
__global__ void embed_kernel(const float* __restrict__ values, const float* __restrict__ times,
                             const int* __restrict__ vars,
                             const float* __restrict__ W1t, const float* __restrict__ b1t,
                             const float* __restrict__ W2t,
                             const float* __restrict__ W1v, const float* __restrict__ b1v,
                             const float* __restrict__ W2v,
                             const float* __restrict__ vtab)
{
    int tok = blockIdx.x;
    int b = tok >> 11, j = tok & 2047;
    int d = threadIdx.x;
    if (j >= g_npad[b]) return;
    size_t oidx = (size_t)tok*DD + d;
    if (j >= g_nb[b]) {
        g_x[oidx] = 0.f;
        g_x0[oidx] = __float2bfloat16(0.f);
        g_x1[oidx] = __float2bfloat16(0.f);
        g_x2[oidx] = __float2bfloat16(0.f);
        return;
    }
    int l = g_idx[tok];
    __shared__ float tt[INTD], vv[INTD];
    if (d < INTD) {
        float t = times[b*SL + l], v = values[b*SL + l];
        tt[d] = tanhf(t * W1t[d] + b1t[d]);
        vv[d] = tanhf(v * W1v[d] + b1v[d]);
    }
    __syncthreads();
    int var = vars[b*SL + l];
    float acc = vtab[var*DD + d];
#pragma unroll
    for (int i = 0; i < INTD; i++)
        acc += tt[i]*W2t[i*DD+d] + vv[i]*W2v[i*DD+d];
    g_x[oidx] = acc;
    uint16_t h0, h1, h2;
    split3(acc, h0, h1, h2);
    g_x0[oidx] = __ushort_as_bfloat16(h0);
    g_x1[oidx] = __ushort_as_bfloat16(h1);
    g_x2[oidx] = __ushort_as_bfloat16(h2);
}

// ---------------- weight repack ----------------------------------------------
__global__ void wrepack_kernel(const float* __restrict__ Wq, const float* __restrict__ Wk,
                               const float* __restrict__ Wv, const float* __restrict__ Wo,
                               const float* __restrict__ W1, const float* __restrict__ W2,
                               const float* __restrict__ Wf)
{
    int idx = blockIdx.x*256 + threadIdx.x;
    float v;
    if (idx >= WF_OFF) {
        int rr = idx - WF_OFF;
        int n = rr >> 7, k = rr & 127;
        v = Wf[k*DD + n];
    } else {
        int layer = idx >> 17;
        int r = idx & (WT_LAYER-1);
        if (r < WT_WO) {
            int n = r >> 7, k = r & 127;
            int sel = n >> 7;
            int he = n & 127, h = he >> 5, e = he & 31;
            const float* W = sel == 0 ? Wq : (sel == 1 ? Wk : Wv);
            v = W[layer*HH*DD*DKH + h*DD*DKH + k*DKH + e];
        } else if (r < WT_W1) {
            int rr = r - WT_WO; int n = rr >> 7, k = rr & 127;
            v = Wo[layer*DD*DD + k*DD + n];
        } else if (r < WT_W2) {
            int rr = r - WT_W1; int n = rr >> 7, k = rr & 127;
            v = W1[layer*DD*DFF + k*DFF + n];
        } else {
            int rr = r - WT_W2; int n = rr >> 8, k = rr & 255;
            v = W2[layer*DFF*DD + k*DD + n];
        }
    }
    uint16_t h0, h1, h2;
    split3(v, h0, h1, h2);
    g_wt0[idx] = __ushort_as_bfloat16(h0);
    g_wt1[idx] = __ushort_as_bfloat16(h1);
    g_wt2[idx] = __ushort_as_bfloat16(h2);
}

// ---------------- HMMA split GEMM, plane inputs, plane outputs ----------------
// epi: 1 wo (+=gx, write gx+planes) | 2 ffn1 (bias+gelu -> f planes)
//    | 3 ffn2 (bias, +=gx, write gx+planes) | 4 fusion (bias+tanh -> C fp32)
//    | 5 qkv (q/k/v -> per-bh planes)
#define PLANE 10240
#define TG_SMEM (6*PLANE)

__global__ __launch_bounds__(256)
void tgemm_kernel(const __nv_bfloat16* __restrict__ A0,
                  const __nv_bfloat16* __restrict__ A1,
                  const __nv_bfloat16* __restrict__ A2,
                  const __nv_bfloat16* __restrict__ B0,
                  const __nv_bfloat16* __restrict__ B1,
                  const __nv_bfloat16* __restrict__ B2,
                  const float* __restrict__ bias,
                  float* __restrict__ C, int N, int K, int epi)
{
    int bm = blockIdx.y * 128;
    if ((bm & 2047) >= g_npad[bm >> 11]) return;
    int bn = blockIdx.x * 128;

    extern __shared__ char smem[];
    uint16_t (*sA0)[40] = (uint16_t(*)[40])(smem);
    uint16_t (*sA1)[40] = (uint16_t(*)[40])(smem + PLANE);
    uint16_t (*sA2)[40] = (uint16_t(*)[40])(smem + 2*PLANE);
    uint16_t (*sB0)[40] = (uint16_t(*)[40])(smem + 3*PLANE);
    uint16_t (*sB1)[40] = (uint16_t(*)[40])(smem + 4*PLANE);
    uint16_t (*sB2)[40] = (uint16_t(*)[40])(smem + 5*PLANE);

    int tid = threadIdx.x, wid = tid >> 5, lane = tid & 31;
    int wm = (wid & 3) * 32, wn = (wid >> 2) * 64;

    float acc[2][8][4];
#pragma unroll
    for (int mi = 0; mi < 2; mi++)
#pragma unroll
        for (int ni = 0; ni < 8; ni++)
#pragma unroll
            for (int c = 0; c < 4; c++) acc[mi][ni][c] = 0.f;

    uint32_t bA0 = smem_u32(sA0), bA1 = smem_u32(sA1), bA2 = smem_u32(sA2);
    uint32_t bB0 = smem_u32(sB0), bB1 = smem_u32(sB1), bB2 = smem_u32(sB2);
    int rowA = lane & 15, colA8 = (lane >> 4) * 8;
    int rowB = ((lane >> 4) << 3) + (lane & 7), colB8 = ((lane >> 3) & 1) * 8;

    for (int k0 = 0; k0 < K; k0 += 32) {
#pragma unroll
        for (int it = 0; it < 4; it++) {
            int idx = tid + it*256;
            int row = idx >> 3, c4 = (idx & 7) * 4;
            size_t aoff = (size_t)(bm + row)*K + k0 + c4;
            *(uint2*)&sA0[row][c4] = *(const uint2*)(A0 + aoff);
            *(uint2*)&sA1[row][c4] = *(const uint2*)(A1 + aoff);
            *(uint2*)&sA2[row][c4] = *(const uint2*)(A2 + aoff);
            size_t goff = (size_t)(bn + row)*K + k0 + c4;
            *(uint2*)&sB0[row][c4] = *(const uint2*)(B0 + goff);
            *(uint2*)&sB1[row][c4] = *(const uint2*)(B1 + goff);
            *(uint2*)&sB2[row][c4] = *(const uint2*)(B2 + goff);
        }
        __syncthreads();

#pragma unroll
        for (int ks = 0; ks < 32; ks += 16) {
            uint32_t a0[2][4], a1[2][4], a2[2][4];
#pragma unroll
            for (int mi = 0; mi < 2; mi++) {
                uint32_t off = ((uint32_t)((wm + mi*16 + rowA)*40 + ks + colA8)) * 2;
                ldsm4(a0[mi], bA0 + off);
                ldsm4(a1[mi], bA1 + off);
                ldsm4(a2[mi], bA2 + off);
            }
#pragma unroll
            for (int pi = 0; pi < 4; pi++) {
                uint32_t off = ((uint32_t)((wn + pi*16 + rowB)*40 + ks + colB8)) * 2;
                uint32_t b0[4], b1[4], b2[4];
                ldsm4(b0, bB0 + off);
                ldsm4(b1, bB1 + off);
                ldsm4(b2, bB2 + off);
#pragma unroll
                for (int mi = 0; mi < 2; mi++)
#pragma unroll
                    for (int nj = 0; nj < 2; nj++) {
                        float* ac = acc[mi][pi*2 + nj];
                        const uint32_t* f0 = &b0[nj*2];
                        const uint32_t* f1 = &b1[nj*2];
                        const uint32_t* f2 = &b2[nj*2];
                        mma16816(ac, a0[mi], f0);
                        mma16816(ac, a0[mi], f1);
                        mma16816(ac, a1[mi], f0);
                        mma16816(ac, a0[mi], f2);
                        mma16816(ac, a1[mi], f1);
                        mma16816(ac, a2[mi], f0);
                    }
            }
        }
        __syncthreads();
    }

    int r0base = bm + wm + (lane >> 2);
    int cbase = wn + (lane & 3) * 2;
#pragma unroll
    for (int mi = 0; mi < 2; mi++) {
#pragma unroll
        for (int ni = 0; ni < 8; ni++) {
            int col = bn + cbase + ni*8;
#pragma unroll
            for (int half = 0; half < 2; half++) {
                int row = r0base + mi*16 + half*8;
                float v0 = acc[mi][ni][half*2], v1 = acc[mi][ni][half*2+1];
                if (epi == 5) {
                    int bb = row >> 11, jj = row & 2047;
                    if (col < 128) {                // Q -> per-bh planes
                        int hh = (col >> 5) & 3, e = col & 31;
                        size_t dst = ((size_t)(bb*4 + hh)*SL + jj)*32 + e;
                        uint16_t a0h, a1h, a2h, b0h, b1h, b2h;
                        split3(v0, a0h, a1h, a2h);
                        split3(v1, b0h, b1h, b2h);
                        *(uint32_t*)(g_q0 + dst) = pack16(a0h, b0h);
                        *(uint32_t*)(g_q1 + dst) = pack16(a1h, b1h);
                        *(uint32_t*)(g_q2 + dst) = pack16(a2h, b2h);
                    } else {
                        int cc = col - 128;
                        int sel = cc >> 7;
                        int hh = (cc >> 5) & 3, e = cc & 31;
                        size_t dst = ((size_t)(bb*4 + hh)*SL + jj)*32 + e;
                        if (sel == 0) {
                            uint16_t a0h, a1h, a2h, b0h, b1h, b2h;
                            split3(v0, a0h, a1h, a2h);
                            split3(v1, b0h, b1h, b2h);
                            *(uint32_t*)(g_k0 + dst) = pack16(a0h, b0h);
                            *(uint32_t*)(g_k1 + dst) = pack16(a1h, b1h);
                            *(uint32_t*)(g_k2 + dst) = pack16(a2h, b2h);
                        } else {
                            uint16_t a0h, a1h, b0h, b1h;
                            split2(v0, a0h, a1h);
                            split2(v1, b0h, b1h);
                            *(uint32_t*)(g_v0 + dst) = pack16(a0h, b0h);
                            *(uint32_t*)(g_v1 + dst) = pack16(a1h, b1h);
                        }
                    }
                    continue;
                }
                if (epi == 2) {                      // FFN1: bias+gelu -> f planes
                    v0 += bias[col]; v1 += bias[col+1];
                    v0 = 0.5f*v0*(1.f + erff(v0*0.7071067811865476f));
                    v1 = 0.5f*v1*(1.f + erff(v1*0.7071067811865476f));
                    size_t dst = (size_t)row*DFF + col;
                    uint16_t a0h, a1h, a2h, b0h, b1h, b2h;
                    split3(v0, a0h, a1h, a2h);
                    split3(v1, b0h, b1h, b2h);
                    *(uint32_t*)(g_f0 + dst) = pack16(a0h, b0h);
                    *(uint32_t*)(g_f1 + dst) = pack16(a1h, b1h);
                    *(uint32_t*)(g_f2 + dst) = pack16(a2h, b2h);
                    continue;
                }
                float* Cp = C + (size_t)row*N + col;
                if (epi >= 3) { v0 += bias[col]; v1 += bias[col+1]; }
                if (epi == 4) { v0 = tanhf(v0); v1 = tanhf(v1); }
                if (epi == 1 || epi == 3) {
                    float2 o = *(const float2*)Cp;
                    v0 += o.x; v1 += o.y;
                }
                *(float2*)Cp = make_float2(v0, v1);
                if (epi == 1 || epi == 3) {          // update x planes
                    size_t dst = (size_t)row*DD + col;
                    uint16_t a0h, a1h, a2h, b0h, b1h, b2h;
                    split3(v0, a0h, a1h, a2h);
                    split3(v1, b0h, b1h, b2h);
                    *(uint32_t*)(g_x0 + dst) = pack16(a0h, b0h);
                    *(uint32_t*)(g_x1 + dst) = pack16(a1h, b1h);
                    *(uint32_t*)(g_x2 + dst) = pack16(a2h, b2h);
                }
            }
        }
    }
}

// ---------------- HMMA flash attention ---------------------------------------
// block: 8 warps, 128 queries x one (b,h); key tiles of 64, cp.async double-buffered
#define KPLANE 5120
#define QPLANE 10240
#define FL_SQ   0
#define FL_BUF  (3*QPLANE)           // 30720
#define FL_BUFSZ (5*KPLANE)          // 25600
#define FL_SMEM (FL_BUF + 2*FL_BUFSZ)  // 81920

__device__ __forceinline__ void stage_kv_async(uint32_t dstb, int bh, int k0, int tid)
{
#pragma unroll
    for (int it = 0; it < 5; it++) {
        int idx = tid + it*256;
        int plane = idx >> 8;
        int r = (idx >> 2) & 63;
        int e8 = (idx & 3) * 8;
        const __nv_bfloat16* src =
            plane == 0 ? g_k0 : plane == 1 ? g_k1 : plane == 2 ? g_k2 :
            plane == 3 ? g_v0 : g_v1;
        const void* gptr = src + ((size_t)bh*SL + k0 + r)*32 + e8;
        uint32_t dst = dstb + plane*KPLANE + r*80 + e8*2;
        asm volatile("cp.async.cg.shared.global [%0], [%1], 16;"
                     :: "r"(dst), "l"(gptr) : "memory");
    }
    asm volatile("cp.async.commit_group;" ::: "memory");
}

__global__ __launch_bounds__(256)
void flash_kernel()
{
    extern __shared__ char fsm[];
    int bh = blockIdx.y;
    int b = bh >> 2, h = bh & 3;
    int n = g_nb[b];
    int q0 = blockIdx.x * 128;
    if (q0 >= n) return;

    int tid = threadIdx.x, wid = tid >> 5, lane = tid & 31;
    uint32_t sbase = smem_u32(fsm);

    // ---- stage Q (pure plane copies), 128 rows x 3 planes = 1536 uint4 ----
#pragma unroll
    for (int it = 0; it < 6; it++) {
        int idx = tid + it*256;
        int plane = idx >> 9;
        int r = (idx >> 2) & 127;
        int e8 = (idx & 3) * 8;
        const __nv_bfloat16* src = plane == 0 ? g_q0 : plane == 1 ? g_q1 : g_q2;
        uint4 val = *(const uint4*)(src + ((size_t)bh*SL + q0 + r)*32 + e8);
        *(uint4*)(fsm + FL_SQ + plane*QPLANE + r*80 + e8*2) = val;
    }
    __syncthreads();

    uint32_t qf[3][2][4];
    int rowA = lane & 15, colA8 = (lane >> 4) * 8;
#pragma unroll
    for (int p = 0; p < 3; p++)
#pragma unroll
        for (int ks = 0; ks < 2; ks++)
            ldsm4(qf[p][ks], sbase + FL_SQ + p*QPLANE + (wid*16 + rowA)*80 + (ks*16 + colA8)*2);

    float mx[2] = {-INFINITY, -INFINITY};
    float ls[2] = {0.f, 0.f};
    float oa[4][4];
#pragma unroll
    for (int i = 0; i < 4; i++)
#pragma unroll
        for (int u = 0; u < 4; u++) oa[i][u] = 0.f;

    int rowB = ((lane >> 4) << 3) + (lane & 7), colB8 = ((lane >> 3) & 1) * 8;

    int nt = (n + 63) >> 6;
    uint32_t bufb[2] = { sbase + FL_BUF, sbase + FL_BUF + FL_BUFSZ };
    stage_kv_async(bufb[0], bh, 0, tid);
    int cur = 0;

    for (int t = 0; t < nt; t++) {
        int k0 = t*64;
        asm volatile("cp.async.wait_group 0;" ::: "memory");
        __syncthreads();
        if (t + 1 < nt) stage_kv_async(bufb[cur ^ 1], bh, k0 + 64, tid);
        uint32_t kb = bufb[cur];
        uint32_t vb = bufb[cur] + 3*KPLANE;

        // ---- S = Q K^T (6-product RN split) ----
        float sf[8][4];
#pragma unroll
        for (int j = 0; j < 8; j++)
#pragma unroll
            for (int u = 0; u < 4; u++) sf[j][u] = 0.f;

#pragma unroll
        for (int ks = 0; ks < 2; ks++) {
#pragma unroll
            for (int i = 0; i < 4; i++) {
                uint32_t off0 = kb + (i*16 + rowB)*80 + (ks*16 + colB8)*2;
                uint32_t kb0[4], kb1[4], kb2[4];
                ldsm4(kb0, off0);
                ldsm4(kb1, off0 + KPLANE);
                ldsm4(kb2, off0 + 2*KPLANE);
#pragma unroll
                for (int nj = 0; nj < 2; nj++) {
                    float* s = sf[i*2 + nj];
                    const uint32_t* f0 = &kb0[nj*2];
                    const uint32_t* f1 = &kb1[nj*2];
                    const uint32_t* f2 = &kb2[nj*2];
                    mma16816(s, qf[0][ks], f0);
                    mma16816(s, qf[0][ks], f1);
                    mma16816(s, qf[1][ks], f0);
                    mma16816(s, qf[0][ks], f2);
                    mma16816(s, qf[1][ks], f1);
                    mma16816(s, qf[2][ks], f0);
                }
            }
        }

        // ---- tail masking (exact FMIN) ----
        if (k0 + 64 > n) {
            int cb = 2*(lane & 3);
#pragma unroll
            for (int j = 0; j < 8; j++) {
                int c = k0 + 8*j + cb;
                if (c >= n)     { sf[j][0] = FMIN_F; sf[j][2] = FMIN_F; }
                if (c + 1 >= n) { sf[j][1] = FMIN_F; sf[j][3] = FMIN_F; }
            }
        }

        // ---- online softmax ----
#pragma unroll
        for (int rh = 0; rh < 2; rh++) {
            float tm = -INFINITY;
#pragma unroll
            for (int j = 0; j < 8; j++)
                tm = fmaxf(tm, fmaxf(sf[j][rh*2], sf[j][rh*2+1]));
            tm = fmaxf(tm, __shfl_xor_sync(0xFFFFFFFFu, tm, 1));
            tm = fmaxf(tm, __shfl_xor_sync(0xFFFFFFFFu, tm, 2));
            float nm = fmaxf(mx[rh], tm);
            float c = __expf(mx[rh] - nm);
            mx[rh] = nm;
            float ps = 0.f;
#pragma unroll
            for (int j = 0; j < 8; j++) {
                float e0 = __expf(sf[j][rh*2]   - nm);
                float e1 = __expf(sf[j][rh*2+1] - nm);
                sf[j][rh*2] = e0; sf[j][rh*2+1] = e1;
                ps += e0 + e1;
            }
            ls[rh] = ls[rh]*c + ps;
#pragma unroll
            for (int nf = 0; nf < 4; nf++) {
                oa[nf][rh*2]   *= c;
                oa[nf][rh*2+1] *= c;
            }
        }

        // ---- O += P V (P RN 3-plane, V RN 2-plane, 5 products) ----
#pragma unroll
        for (int g = 0; g < 4; g++) {
            float* s0 = sf[2*g];
            float* s1 = sf[2*g+1];
            uint16_t t0[8], t1[8], t2[8];
#pragma unroll
            for (int u = 0; u < 4; u++) split3(s0[u], t0[u],   t1[u],   t2[u]);
#pragma unroll
            for (int u = 0; u < 4; u++) split3(s1[u], t0[4+u], t1[4+u], t2[4+u]);
            uint32_t ap0[4], ap1[4], ap2[4];
#pragma unroll
            for (int u = 0; u < 4; u++) {
                ap0[u] = pack16(t0[2*u], t0[2*u+1]);
                ap1[u] = pack16(t1[2*u], t1[2*u+1]);
                ap2[u] = pack16(t2[2*u], t2[2*u+1]);
            }
#pragma unroll
            for (int nb = 0; nb < 2; nb++) {
                uint32_t v0r[4], v1r[4];
                uint32_t voff = vb + (g*16 + (lane & 15))*80 + (nb*16 + (lane >> 4)*8)*2;
                ldsm4t(v0r, voff);
                ldsm4t(v1r, voff + KPLANE);
#pragma unroll
                for (int nj = 0; nj < 2; nj++) {
                    int nf = nb*2 + nj;
                    mma16816(oa[nf], ap0, &v0r[nj*2]);
                    mma16816(oa[nf], ap0, &v1r[nj*2]);
                    mma16816(oa[nf], ap1, &v0r[nj*2]);
                    mma16816(oa[nf], ap1, &v1r[nj*2]);
                    mma16816(oa[nf], ap2, &v0r[nj*2]);
                }
            }
        }
        cur ^= 1;
    }

    // ---- epilogue: write o planes ----
    float inv[2];
#pragma unroll
    for (int rh = 0; rh < 2; rh++) {
        float l = ls[rh];
        l += __shfl_xor_sync(0xFFFFFFFFu, l, 1);
        l += __shfl_xor_sync(0xFFFFFFFFu, l, 2);
        inv[rh] = 1.f / l;
    }
    int r0 = q0 + wid*16 + (lane >> 2);
    int cb = 2*(lane & 3);
#pragma unroll
    for (int nf = 0; nf < 4; nf++)
#pragma unroll
        for (int rh = 0; rh < 2; rh++) {
            int row = r0 + rh*8;
            float v0 = oa[nf][rh*2]*inv[rh];
            float v1 = oa[nf][rh*2+1]*inv[rh];
            size_t dst = (size_t)(b*SL + row)*DD + h*32 + 8*nf + cb;
            uint16_t a0h, a1h, a2h, b0h, b1h, b2h;
            split3(v0, a0h, a1h, a2h);
            split3(v1, b0h, b1h, b2h);
            *(uint32_t*)(g_o0 + dst) = pack16(a0h, b0h);
            *(uint32_t*)(g_o1 + dst) = pack16(a1h, b1h);
            *(uint32_t*)(g_o2 + dst) = pack16(a2h, b2h);
        }
}

// ---------------- fusion reduce: att[tok] = tanh(xWf+bf) . uf ----------------
__global__ void fuse_reduce_kernel(const float* __restrict__ uf)
{
    int wid = threadIdx.x >> 5, lane = threadIdx.x & 31;
    int tok = blockIdx.x*8 + wid;
    int b = tok >> 11, j = tok & 2047;
    if (j >= g_nb[b]) return;
    const float* f = g_ff + (size_t)tok*DD;
    float acc = 0.f;
#pragma unroll
    for (int t = 0; t < 4; t++) {
        int d = lane + t*32;
        acc += f[d] * uf[d];
    }
    acc += __shfl_xor_sync(0xFFFFFFFFu, acc, 16);
    acc += __shfl_xor_sync(0xFFFFFFFFu, acc, 8);
    acc += __shfl_xor_sync(0xFFFFFFFFu, acc, 4);
    acc += __shfl_xor_sync(0xFFFFFFFFu, acc, 2);
    acc += __shfl_xor_sync(0xFFFFFFFFu, acc, 1);
    if (lane == 0) g_att[tok] = acc;
}

// ---------------- masked softmax pooling -------------------------------------
__global__ void pool_kernel()
{
    int b = blockIdx.x;
    int n = g_nb[b];
    int tid = threadIdx.x;
    __shared__ float w[SL];
    __shared__ float red[256];
    float mx = -INFINITY;
    for (int l = tid; l < n; l += 256) mx = fmaxf(mx, g_att[b*SL + l]);
    red[tid] = mx; __syncthreads();
    for (int s = 128; s > 0; s >>= 1) { if (tid < s) red[tid] = fmaxf(red[tid], red[tid+s]); __syncthreads(); }
    mx = red[0]; __syncthreads();
    float sum = 0.f;
    for (int l = tid; l < n; l += 256) { float e = __expf(g_att[b*SL+l] - mx); w[l] = e; sum += e; }
    red[tid] = sum; __syncthreads();
    for (int s = 128; s > 0; s >>= 1) { if (tid < s) red[tid] += red[tid+s]; __syncthreads(); }
    float inv = 1.f / red[0];
    __syncthreads();
    int d = tid & 127, half = tid >> 7;
    float acc = 0.f;
    for (int l = half; l < n; l += 2)
        acc += w[l]*g_x[((size_t)b*SL + l)*DD + d];
    red[tid] = acc; __syncthreads();
    if (tid < 128) g_ts[b*DD + tid] = (red[tid] + red[tid+128])*inv;
}

// ---------------- demographics MLP -------------------------------------------
__global__ void demo_kernel(const float* __restrict__ demo, const float* __restrict__ Wd1,
                            const float* __restrict__ bd1, const float* __restrict__ Wd2,
                            const float* __restrict__ bd2)
{
    int b = blockIdx.x;
    int tid = threadIdx.x;
    __shared__ float ds[DMG];
    __shared__ float hs[256];
    if (tid < DMG) ds[tid] = demo[b*DMG + tid];
    __syncthreads();
    float a = bd1[tid];
#pragma unroll
    for (int k = 0; k < DMG; k++) a += ds[k]*Wd1[k*256 + tid];
    hs[tid] = tanhf(a);
    __syncthreads();
    if (tid < DD) {
        float a2 = bd2[tid];
#pragma unroll 8
        for (int k = 0; k < 256; k++) a2 += hs[k]*Wd2[k*DD + tid];
        g_demo[b*DD + tid] = a2;
    }
}

// ---------------- head --------------------------------------------------------
__global__ void head_kernel(const float* __restrict__ Wh, const float* __restrict__ bh,
                            float* __restrict__ out)
{
    int b = blockIdx.x;
    int tid = threadIdx.x;
    __shared__ float es[256];
    es[tid] = (tid < 128) ? g_ts[b*DD + tid] : g_demo[b*DD + (tid - 128)];
    __syncthreads();
    if (tid < NF) {
        float acc = bh[tid];
#pragma unroll 8
        for (int k = 0; k < 256; k++) acc += es[k]*Wh[k*NF + tid];
        out[b*NF + tid] = acc;
    }
}

// ---------------- orchestration ------------------------------------------------
extern "C" void kernel_launch(void* const* d_in, const int* in_sizes, int n_in,
                              void* d_out, int out_size)
{
    const float* values = (const float*)d_in[0];
    const float* times  = (const float*)d_in[1];
    const int*   vars   = (const int*)d_in[2];
    const void*  maskraw = d_in[3];
    const float* demo   = (const float*)d_in[4];
    const float* W1t = (const float*)d_in[5];
    const float* b1t = (const float*)d_in[6];
    const float* W2t = (const float*)d_in[7];
    const float* W1v = (const float*)d_in[8];
    const float* b1v = (const float*)d_in[9];
    const float* W2v = (const float*)d_in[10];
    const float* vtab = (const float*)d_in[11];
    const float* Wq = (const float*)d_in[12];
    const float* Wk = (const float*)d_in[13];
    const float* Wv = (const float*)d_in[14];
    const float* Wo = (const float*)d_in[15];
    const float* W1 = (const float*)d_in[16];
    const float* b1 = (const float*)d_in[17];
    const float* W2 = (const float*)d_in[18];
    const float* b2 = (const float*)d_in[19];
    const float* Wf = (const float*)d_in[20];
    const float* bf = (const float*)d_in[21];
    const float* uf = (const float*)d_in[22];
    const float* Wd1 = (const float*)d_in[23];
    const float* bd1 = (const float*)d_in[24];
    const float* Wd2 = (const float*)d_in[25];
    const float* bd2 = (const float*)d_in[26];
    const float* Wh = (const float*)d_in[27];
    const float* bh = (const float*)d_in[28];
    float* out = (float*)d_out;

    float *xp, *ffp;
    __nv_bfloat16 *w0p, *w1p, *w2p;
    __nv_bfloat16 *x0p, *x1p, *x2p, *f0p, *f1p, *f2p, *o0p, *o1p, *o2p;
    cudaGetSymbolAddress((void**)&xp,   g_x);
    cudaGetSymbolAddress((void**)&ffp,  g_ff);
    cudaGetSymbolAddress((void**)&w0p,  g_wt0);
    cudaGetSymbolAddress((void**)&w1p,  g_wt1);
    cudaGetSymbolAddress((void**)&w2p,  g_wt2);
    cudaGetSymbolAddress((void**)&x0p,  g_x0);
    cudaGetSymbolAddress((void**)&x1p,  g_x1);
    cudaGetSymbolAddress((void**)&x2p,  g_x2);
    cudaGetSymbolAddress((void**)&f0p,  g_f0);
    cudaGetSymbolAddress((void**)&f1p,  g_f1);
    cudaGetSymbolAddress((void**)&f2p,  g_f2);
    cudaGetSymbolAddress((void**)&o0p,  g_o0);
    cudaGetSymbolAddress((void**)&o1p,  g_o1);
    cudaGetSymbolAddress((void**)&o2p,  g_o2);

    cudaFuncSetAttribute(tgemm_kernel, cudaFuncAttributeMaxDynamicSharedMemorySize, TG_SMEM);
    cudaFuncSetAttribute(flash_kernel, cudaFuncAttributeMaxDynamicSharedMemorySize, FL_SMEM);

    mask_reset_kernel<<<1, 32>>>();
    mask_scan_kernel<<<NTOK/4/256, 256>>>((const unsigned int*)maskraw);
    mask_convert_kernel<<<NTOK/256, 256>>>(maskraw);
    compact_kernel<<<BB, 256>>>();

    wrepack_kernel<<<WT_TOTAL/256, 256>>>(Wq, Wk, Wv, Wo, W1, W2, Wf);
    demo_kernel<<<BB, 256>>>(demo, Wd1, bd1, Wd2, bd2);
    embed_kernel<<<NTOK, 128>>>(values, times, vars, W1t, b1t, W2t, W1v, b1v, W2v, vtab);

    for (int i = 0; i < NLAY; i++) {
        const __nv_bfloat16* l0 = w0p + i*WT_LAYER;
        const __nv_bfloat16* l1 = w1p + i*WT_LAYER;
        const __nv_bfloat16* l2 = w2p + i*WT_LAYER;
        // QKV: A = x planes; outputs go to q/k/v per-bh planes (epi=5)
        tgemm_kernel<<<dim3(3, NTOK/128), 256, TG_SMEM>>>(x0p, x1p, x2p,
                                                          l0 + WT_QKV, l1 + WT_QKV, l2 + WT_QKV,
                                                          nullptr, xp, 384, 128, 5);
        flash_kernel<<<dim3(SL/128, BB*HH), 256, FL_SMEM>>>();
        // Wo: A = o planes; += residual, write fp32 x + x planes (epi=1)
        tgemm_kernel<<<dim3(1, NTOK/128), 256, TG_SMEM>>>(o0p, o1p, o2p,
                                                          l0 + WT_WO, l1 + WT_WO, l2 + WT_WO,
                                                          nullptr, xp, 128, 128, 1);
        // FFN1: A = x planes; bias+gelu -> f planes (epi=2)
        tgemm_kernel<<<dim3(2, NTOK/128), 256, TG_SMEM>>>(x0p, x1p, x2p,
                                                          l0 + WT_W1, l1 + WT_W1, l2 + WT_W1,
                                                          b1 + i*DFF, xp, 256, 128, 2);
        // FFN2: A = f planes; bias + residual, write fp32 x + x planes (epi=3)
        tgemm_kernel<<<dim3(1, NTOK/128), 256, TG_SMEM>>>(f0p, f1p, f2p,
                                                          l0 + WT_W2, l1 + WT_W2, l2 + WT_W2,
                                                          b2 + i*DD, xp, 128, 256, 3);
    }

    // fusion: A = x planes; bias+tanh -> g_ff fp32 (epi=4), then dot with uf
    tgemm_kernel<<<dim3(1, NTOK/128), 256, TG_SMEM>>>(x0p, x1p, x2p,
                                                      w0p + WF_OFF, w1p + WF_OFF, w2p + WF_OFF,
                                                      bf, ffp, 128, 128, 4);
    fuse_reduce_kernel<<<NTOK/8, 256>>>(uf);
    pool_kernel<<<BB, 256>>>();
    head_kernel<<<BB, 256>>>(Wh, bh, out);
}

// round 14
// speedup vs baseline: 1.1326x; 1.1326x over previous
#include <cuda_runtime.h>
#include <cuda_bf16.h>
#include <math.h>
#include <stdint.h>

#define BB   16
#define SL   2048
#define DD   128
#define HH   4
#define NLAY 4
#define DKH  32
#define DFF  256
#define NF   129
#define DMG  16
#define INTD 11
#define NTOK (BB*SL)
#define FMIN_F (-3.402823466e38f)

// per-layer transposed bf16 weight planes: qkv[384x128] | wo[128x128] | w1[256x128] | w2[128x256]
#define WT_LAYER 131072
#define WT_QKV   0
#define WT_WO    49152
#define WT_W1    65536
#define WT_W2    98304
#define WF_OFF   (NLAY*WT_LAYER)          // Wf plane appended after layer weights
#define WT_TOTAL (WF_OFF + DD*DD)

// ---------------- scratch (device globals: allocation-free) ----------------
__device__ float g_x[NTOK*DD];
__device__ float g_qkv[NTOK*3*DD];
__device__ float g_o[NTOK*DD];
__device__ float g_ff[NTOK*DFF];
__device__ float g_demo[BB*DD];
__device__ float g_att[BB*SL];
__device__ float g_ts[BB*DD];
__device__ __nv_bfloat16 g_wt0[WT_TOTAL];
__device__ __nv_bfloat16 g_wt1[WT_TOTAL];
__device__ __nv_bfloat16 g_wt2[WT_TOTAL];
// per-(b,h) split planes of K (3) and V (2): [((b*4+h)*SL + j)*32 + e]
#define PL_ELEMS (BB*HH*SL*DKH)
__device__ __nv_bfloat16 g_k0[PL_ELEMS];
__device__ __nv_bfloat16 g_k1[PL_ELEMS];
__device__ __nv_bfloat16 g_k2[PL_ELEMS];
__device__ __nv_bfloat16 g_v0[PL_ELEMS];
__device__ __nv_bfloat16 g_v1[PL_ELEMS];
__device__ int g_idx[NTOK];
__device__ int g_nb[BB];
__device__ int g_npad[BB];
__device__ int g_cnt[2];

// ---------------- PTX helpers -------------------------------------------------
__device__ __forceinline__ uint32_t smem_u32(const void* p) {
    uint32_t a;
    asm("{ .reg .u64 t; cvta.to.shared.u64 t, %1; cvt.u32.u64 %0, t; }" : "=r"(a) : "l"(p));
    return a;
}
__device__ __forceinline__ void ldsm4(uint32_t* r, uint32_t addr) {
    asm volatile("ldmatrix.sync.aligned.m8n8.x4.shared.b16 {%0,%1,%2,%3}, [%4];"
        : "=r"(r[0]), "=r"(r[1]), "=r"(r[2]), "=r"(r[3]) : "r"(addr));
}
__device__ __forceinline__ void ldsm4t(uint32_t* r, uint32_t addr) {
    asm volatile("ldmatrix.sync.aligned.m8n8.x4.trans.shared.b16 {%0,%1,%2,%3}, [%4];"
        : "=r"(r[0]), "=r"(r[1]), "=r"(r[2]), "=r"(r[3]) : "r"(addr));
}
__device__ __forceinline__ void mma16816(float* d, const uint32_t* a, const uint32_t* b) {
    asm volatile("mma.sync.aligned.m16n8k16.row.col.f32.bf16.bf16.f32 "
        "{%0,%1,%2,%3}, {%4,%5,%6,%7}, {%8,%9}, {%0,%1,%2,%3};"
        : "+f"(d[0]), "+f"(d[1]), "+f"(d[2]), "+f"(d[3])
        : "r"(a[0]), "r"(a[1]), "r"(a[2]), "r"(a[3]), "r"(b[0]), "r"(b[1]));
}
__device__ __forceinline__ void split3(float x, uint16_t& h0, uint16_t& h1, uint16_t& h2) {
    __nv_bfloat16 b0 = __float2bfloat16(x);
    float r1 = x - __bfloat162float(b0);
    __nv_bfloat16 b1 = __float2bfloat16(r1);
    float r2 = r1 - __bfloat162float(b1);
    __nv_bfloat16 b2 = __float2bfloat16(r2);
    h0 = __bfloat16_as_ushort(b0);
    h1 = __bfloat16_as_ushort(b1);
    h2 = __bfloat16_as_ushort(b2);
}
__device__ __forceinline__ void split2(float x, uint16_t& h0, uint16_t& h1) {
    __nv_bfloat16 b0 = __float2bfloat16(x);
    float r1 = x - __bfloat162float(b0);
    __nv_bfloat16 b1 = __float2bfloat16(r1);
    h0 = __bfloat16_as_ushort(b0);
    h1 = __bfloat16_as_ushort(b1);
}
__device__ __forceinline__ uint32_t pack16(uint16_t lo, uint16_t hi) {
    return (uint32_t)lo | ((uint32_t)hi << 16);
}

// ---------------- mask dtype detection ---------------------------------------
__global__ void mask_reset_kernel() {
    if (threadIdx.x < 2) g_cnt[threadIdx.x] = 0;
}
__global__ void mask_scan_kernel(const unsigned int* __restrict__ w) {
    int i = blockIdx.x*256 + threadIdx.x;
    unsigned int v = w[i];
    if (v > 1u) atomicOr(&g_cnt[0], 1);
    if (v != 0u && v != 0x3F800000u) atomicOr(&g_cnt[1], 1);
}

// ---------------- stable compaction (dtype dispatch fused) -------------------
__global__ void compact_kernel(const void* __restrict__ p)
{
    int b = blockIdx.x, tid = threadIdx.x;
    __shared__ int sc[256];
    __shared__ int sbase;
    int mode = (g_cnt[0] == 0) ? 0 : (g_cnt[1] == 0) ? 1 : 2;
    if (tid == 0) sbase = 0;
    __syncthreads();
    for (int c = 0; c < SL; c += 256) {
        int l = c + tid;
        int m;
        if (mode == 0)      m = ((const int*)p)[b*SL + l] != 0;
        else if (mode == 1) m = ((const float*)p)[b*SL + l] != 0.0f;
        else                m = ((const unsigned char*)p)[b*SL + l] != 0;
        sc[tid] = m;
        __syncthreads();
#pragma unroll
        for (int s = 1; s < 256; s <<= 1) {
            int v = (tid >= s) ? sc[tid - s] : 0;
            __syncthreads();
            sc[tid] += v;
            __syncthreads();
        }
        int pos = sbase + sc[tid] - m;
        if (m) g_idx[b*SL + pos] = l;
        int tot = sc[255];
        __syncthreads();
        if (tid == 0) sbase += tot;
        __syncthreads();
    }
    if (tid == 0) { g_nb[b] = sbase; g_npad[b] = (sbase + 127) & ~127; }
}

// ---------------- embedding (compacted) --------------------------------------
__global__ void embed_kernel(const float* __restrict__ values, const float* __restrict__ times,
                             const int* __restrict__ vars,
                             const float* __restrict__ W1t, const float* __restrict__ b1t,
                             const float* __restrict__ W2t,
                             const float* __restrict__ W1v, const float* __restrict__ b1v,
                             const float* __restrict__ W2v,
                             const float* __restrict__ vtab)
{
    int tok = blockIdx.x;
    int b = tok >> 11, j = tok & 2047;
    int d = threadIdx.x;
    if (j >= g_npad[b]) return;
    if (j >= g_nb[b]) { g_x[(size_t)tok*DD + d] = 0.f; return; }
    int l = g_idx[tok];
    __shared__ float tt[INTD], vv[INTD];
    if (d < INTD) {
        float t = times[b*SL + l], v = values[b*SL + l];
        tt[d] = tanhf(t * W1t[d] + b1t[d]);
        vv[d] = tanhf(v * W1v[d] + b1v[d]);
    }
    __syncthreads();
    int var = vars[b*SL + l];
    float acc = vtab[var*DD + d];
#pragma unroll
    for (int i = 0; i < INTD; i++)
        acc += tt[i]*W2t[i*DD+d] + vv[i]*W2v[i*DD+d];
    g_x[(size_t)tok*DD + d] = acc;
}

// ---------------- weight repack: transpose + bf16 3-way split ----------------
__global__ void wrepack_kernel(const float* __restrict__ Wq, const float* __restrict__ Wk,
                               const float* __restrict__ Wv, const float* __restrict__ Wo,
                               const float* __restrict__ W1, const float* __restrict__ W2,
                               const float* __restrict__ Wf)
{
    int idx = blockIdx.x*256 + threadIdx.x;      // < WT_TOTAL
    float v;
    if (idx >= WF_OFF) {             // fusion Wf: [dout][din] transposed
        int rr = idx - WF_OFF;
        int n = rr >> 7, k = rr & 127;
        v = Wf[k*DD + n];
    } else {
        int layer = idx >> 17;
        int r = idx & (WT_LAYER-1);
        if (r < WT_WO) {                 // qkv: n = sel*128+h*32+e, k = d
            int n = r >> 7, k = r & 127;
            int sel = n >> 7;
            int he = n & 127, h = he >> 5, e = he & 31;
            const float* W = sel == 0 ? Wq : (sel == 1 ? Wk : Wv);
            v = W[layer*HH*DD*DKH + h*DD*DKH + k*DKH + e];
        } else if (r < WT_W1) {          // wo: [dout][din]
            int rr = r - WT_WO; int n = rr >> 7, k = rr & 127;
            v = Wo[layer*DD*DD + k*DD + n];
        } else if (r < WT_W2) {          // w1: [f][d]
            int rr = r - WT_W1; int n = rr >> 7, k = rr & 127;
            v = W1[layer*DD*DFF + k*DFF + n];
        } else {                         // w2: [d][f]
            int rr = r - WT_W2; int n = rr >> 8, k = rr & 255;
            v = W2[layer*DFF*DD + k*DD + n];
        }
    }
    uint16_t h0, h1, h2;
    split3(v, h0, h1, h2);
    g_wt0[idx] = __ushort_as_bfloat16(h0);
    g_wt1[idx] = __ushort_as_bfloat16(h1);
    g_wt2[idx] = __ushort_as_bfloat16(h2);
}

// ---------------- HMMA 3-way-split GEMM: C tile 128x128 ----------------------
// epi: 0 none | 1 +=C | 2 bias+gelu | 3 bias+ +=C | 4 bias+tanh | 5 qkv (q->C, k/v->split planes)
#define PLANE 10240                        // 128 rows * 40 cols * 2B (tgemm planes)
#define TG_SMEM (6*PLANE)

__global__ __launch_bounds__(256)
void tgemm_kernel(const float* __restrict__ A,
                  const __nv_bfloat16* __restrict__ B0,
                  const __nv_bfloat16* __restrict__ B1,
                  const __nv_bfloat16* __restrict__ B2,
                  const float* __restrict__ bias,
                  float* __restrict__ C, int N, int K, int epi)
{
    int bm = blockIdx.y * 128;
    if ((bm & 2047) >= g_npad[bm >> 11]) return;
    int bn = blockIdx.x * 128;

    extern __shared__ char smem[];
    uint16_t (*sA0)[40] = (uint16_t(*)[40])(smem);
    uint16_t (*sA1)[40] = (uint16_t(*)[40])(smem + PLANE);
    uint16_t (*sA2)[40] = (uint16_t(*)[40])(smem + 2*PLANE);
    uint16_t (*sB0)[40] = (uint16_t(*)[40])(smem + 3*PLANE);
    uint16_t (*sB1)[40] = (uint16_t(*)[40])(smem + 4*PLANE);
    uint16_t (*sB2)[40] = (uint16_t(*)[40])(smem + 5*PLANE);

    int tid = threadIdx.x, wid = tid >> 5, lane = tid & 31;
    int wm = (wid & 3) * 32, wn = (wid >> 2) * 64;

    float acc[2][8][4];
#pragma unroll
    for (int mi = 0; mi < 2; mi++)
#pragma unroll
        for (int ni = 0; ni < 8; ni++)
#pragma unroll
            for (int c = 0; c < 4; c++) acc[mi][ni][c] = 0.f;

    uint32_t bA0 = smem_u32(sA0), bA1 = smem_u32(sA1), bA2 = smem_u32(sA2);
    uint32_t bB0 = smem_u32(sB0), bB1 = smem_u32(sB1), bB2 = smem_u32(sB2);
    int rowA = lane & 15, colA8 = (lane >> 4) * 8;
    int rowB = ((lane >> 4) << 3) + (lane & 7), colB8 = ((lane >> 3) & 1) * 8;

    for (int k0 = 0; k0 < K; k0 += 32) {
#pragma unroll
        for (int it = 0; it < 4; it++) {
            int idx = tid + it*256;             // 1024 float4-groups
            int row = idx >> 3, c4 = (idx & 7) * 4;
            float4 a = *(const float4*)(A + (size_t)(bm + row)*K + k0 + c4);
            float av[4] = {a.x, a.y, a.z, a.w};
            uint16_t p0[4], p1[4], p2[4];
#pragma unroll
            for (int u = 0; u < 4; u++) split3(av[u], p0[u], p1[u], p2[u]);
            *(uint2*)&sA0[row][c4] = *(uint2*)p0;
            *(uint2*)&sA1[row][c4] = *(uint2*)p1;
            *(uint2*)&sA2[row][c4] = *(uint2*)p2;
        }
#pragma unroll
        for (int it = 0; it < 4; it++) {
            int idx = tid + it*256;
            int row = idx >> 3, c4 = (idx & 7) * 4;
            size_t goff = (size_t)(bn + row)*K + k0 + c4;
            *(uint2*)&sB0[row][c4] = *(const uint2*)(B0 + goff);
            *(uint2*)&sB1[row][c4] = *(const uint2*)(B1 + goff);
            *(uint2*)&sB2[row][c4] = *(const uint2*)(B2 + goff);
        }
        __syncthreads();

#pragma unroll
        for (int ks = 0; ks < 32; ks += 16) {
            uint32_t a0[2][4], a1[2][4], a2[2][4];
#pragma unroll
            for (int mi = 0; mi < 2; mi++) {
                uint32_t off = ((uint32_t)((wm + mi*16 + rowA)*40 + ks + colA8)) * 2;
                ldsm4(a0[mi], bA0 + off);
                ldsm4(a1[mi], bA1 + off);
                ldsm4(a2[mi], bA2 + off);
            }
#pragma unroll
            for (int pi = 0; pi < 4; pi++) {
                uint32_t off = ((uint32_t)((wn + pi*16 + rowB)*40 + ks + colB8)) * 2;
                uint32_t b0[4], b1[4], b2[4];
                ldsm4(b0, bB0 + off);
                ldsm4(b1, bB1 + off);
                ldsm4(b2, bB2 + off);
#pragma unroll
                for (int mi = 0; mi < 2; mi++)
#pragma unroll
                    for (int nj = 0; nj < 2; nj++) {
                        float* ac = acc[mi][pi*2 + nj];
                        const uint32_t* f0 = &b0[nj*2];
                        const uint32_t* f1 = &b1[nj*2];
                        const uint32_t* f2 = &b2[nj*2];
                        mma16816(ac, a0[mi], f0);
                        mma16816(ac, a0[mi], f1);
                        mma16816(ac, a1[mi], f0);
                        mma16816(ac, a0[mi], f2);
                        mma16816(ac, a1[mi], f1);
                        mma16816(ac, a2[mi], f0);
                    }
            }
        }
        __syncthreads();
    }

    int r0base = bm + wm + (lane >> 2);
    int cbase = wn + (lane & 3) * 2;
#pragma unroll
    for (int mi = 0; mi < 2; mi++) {
#pragma unroll
        for (int ni = 0; ni < 8; ni++) {
            int col = bn + cbase + ni*8;
#pragma unroll
            for (int half = 0; half < 2; half++) {
                int row = r0base + mi*16 + half*8;
                float v0 = acc[mi][ni][half*2], v1 = acc[mi][ni][half*2+1];
                if (epi == 5) {
                    if (col < 128) {
                        *(float2*)(C + (size_t)row*N + col) = make_float2(v0, v1);
                    } else {
                        int cc = col - 128;
                        int sel = cc >> 7;
                        int hh = (cc >> 5) & 3;
                        int e  = cc & 31;
                        int bb = row >> 11, jj = row & 2047;
                        size_t dst = ((size_t)(bb*4 + hh)*SL + jj)*32 + e;
                        if (sel == 0) {
                            uint16_t a0h, a1h, a2h, b0h, b1h, b2h;
                            split3(v0, a0h, a1h, a2h);
                            split3(v1, b0h, b1h, b2h);
                            *(uint32_t*)(g_k0 + dst) = pack16(a0h, b0h);
                            *(uint32_t*)(g_k1 + dst) = pack16(a1h, b1h);
                            *(uint32_t*)(g_k2 + dst) = pack16(a2h, b2h);
                        } else {
                            uint16_t a0h, a1h, b0h, b1h;
                            split2(v0, a0h, a1h);
                            split2(v1, b0h, b1h);
                            *(uint32_t*)(g_v0 + dst) = pack16(a0h, b0h);
                            *(uint32_t*)(g_v1 + dst) = pack16(a1h, b1h);
                        }
                    }
                    continue;
                }
                float* Cp = C + (size_t)row*N + col;
                if (epi >= 2) {
                    v0 += bias[col]; v1 += bias[col+1];
                }
                if (epi == 2) {
                    v0 = 0.5f*v0*(1.f + erff(v0*0.7071067811865476f));
                    v1 = 0.5f*v1*(1.f + erff(v1*0.7071067811865476f));
                }
                if (epi == 4) {
                    v0 = tanhf(v0);
                    v1 = tanhf(v1);
                }
                if (epi == 1 || epi == 3) {
                    float2 o = *(const float2*)Cp;
                    v0 += o.x; v1 += o.y;
                }
                *(float2*)Cp = make_float2(v0, v1);
            }
        }
    }
}

// ---------------- HMMA flash attention ---------------------------------------
// block: 8 warps, 128 queries x one (b,h); key tiles of 64, cp.async double-buffered
#define KPLANE 5120                  // one [64][40] uint16 KV plane
#define QPLANE 10240                 // one [128][40] uint16 Q plane
#define FL_SQ   0
#define FL_BUF  (3*QPLANE)           // 30720
#define FL_BUFSZ (5*KPLANE)          // K0 K1 K2 V0 V1 = 25600
#define FL_SMEM (FL_BUF + 2*FL_BUFSZ)  // 81920

__device__ __forceinline__ void stage_kv_async(uint32_t dstb, int bh, int k0, int tid)
{
#pragma unroll
    for (int it = 0; it < 5; it++) {
        int idx = tid + it*256;             // 1280 uint4
        int plane = idx >> 8;               // 0..4
        int r = (idx >> 2) & 63;
        int e8 = (idx & 3) * 8;
        const __nv_bfloat16* src =
            plane == 0 ? g_k0 : plane == 1 ? g_k1 : plane == 2 ? g_k2 :
            plane == 3 ? g_v0 : g_v1;
        const void* gptr = src + ((size_t)bh*SL + k0 + r)*32 + e8;
        uint32_t dst = dstb + plane*KPLANE + r*80 + e8*2;
        asm volatile("cp.async.cg.shared.global [%0], [%1], 16;"
                     :: "r"(dst), "l"(gptr) : "memory");
    }
    asm volatile("cp.async.commit_group;" ::: "memory");
}

__global__ __launch_bounds__(256)
void flash_kernel()
{
    extern __shared__ char fsm[];
    int bh = blockIdx.y;
    int b = bh >> 2, h = bh & 3;
    int n = g_nb[b];
    int q0 = blockIdx.x * 128;
    if (q0 >= n) return;

    int tid = threadIdx.x, wid = tid >> 5, lane = tid & 31;
    uint32_t sbase = smem_u32(fsm);

    // ---- stage Q (fp32 -> RN 3-plane split), 128 rows ----
#pragma unroll
    for (int it = 0; it < 4; it++) {
        int idx = tid + it*256;                 // 1024 float4-groups
        int row = idx >> 3, c4 = (idx & 7) * 4;
        float4 f = *(const float4*)(g_qkv + (size_t)(b*SL + q0 + row)*384 + h*32 + c4);
        float av[4] = {f.x, f.y, f.z, f.w};
        uint16_t p0[4], p1[4], p2[4];
#pragma unroll
        for (int u = 0; u < 4; u++) split3(av[u], p0[u], p1[u], p2[u]);
        *(uint2*)(fsm + FL_SQ + 0*QPLANE + row*80 + c4*2) = *(uint2*)p0;
        *(uint2*)(fsm + FL_SQ + 1*QPLANE + row*80 + c4*2) = *(uint2*)p1;
        *(uint2*)(fsm + FL_SQ + 2*QPLANE + row*80 + c4*2) = *(uint2*)p2;
    }
    __syncthreads();

    // Q fragments held in registers for the whole kernel (warp wid owns rows wid*16..+16)
    uint32_t qf[3][2][4];
    int rowA = lane & 15, colA8 = (lane >> 4) * 8;
#pragma unroll
    for (int p = 0; p < 3; p++)
#pragma unroll
        for (int ks = 0; ks < 2; ks++)
            ldsm4(qf[p][ks], sbase + FL_SQ + p*QPLANE + (wid*16 + rowA)*80 + (ks*16 + colA8)*2);

    float mx[2] = {-INFINITY, -INFINITY};
    float ls[2] = {0.f, 0.f};
    float oa[4][4];
#pragma unroll
    for (int i = 0; i < 4; i++)
#pragma unroll
        for (int u = 0; u < 4; u++) oa[i][u] = 0.f;

    int rowB = ((lane >> 4) << 3) + (lane & 7), colB8 = ((lane >> 3) & 1) * 8;

    int nt = (n + 63) >> 6;
    uint32_t bufb[2] = { sbase + FL_BUF, sbase + FL_BUF + FL_BUFSZ };
    stage_kv_async(bufb[0], bh, 0, tid);
    int cur = 0;

    for (int t = 0; t < nt; t++) {
        int k0 = t*64;
        asm volatile("cp.async.wait_group 0;" ::: "memory");
        __syncthreads();
        if (t + 1 < nt) stage_kv_async(bufb[cur ^ 1], bh, k0 + 64, tid);
        uint32_t kb = bufb[cur];
        uint32_t vb = bufb[cur] + 3*KPLANE;

        // ---- S = Q K^T (6-product RN split) ----
        float sf[8][4];
#pragma unroll
        for (int j = 0; j < 8; j++)
#pragma unroll
            for (int u = 0; u < 4; u++) sf[j][u] = 0.f;

#pragma unroll
        for (int ks = 0; ks < 2; ks++) {
#pragma unroll
            for (int i = 0; i < 4; i++) {       // n16 key groups
                uint32_t off0 = kb + (i*16 + rowB)*80 + (ks*16 + colB8)*2;
                uint32_t kb0[4], kb1[4], kb2[4];
                ldsm4(kb0, off0);
                ldsm4(kb1, off0 + KPLANE);
                ldsm4(kb2, off0 + 2*KPLANE);
#pragma unroll
                for (int nj = 0; nj < 2; nj++) {
                    float* s = sf[i*2 + nj];
                    const uint32_t* f0 = &kb0[nj*2];
                    const uint32_t* f1 = &kb1[nj*2];
                    const uint32_t* f2 = &kb2[nj*2];
                    mma16816(s, qf[0][ks], f0);
                    mma16816(s, qf[0][ks], f1);
                    mma16816(s, qf[1][ks], f0);
                    mma16816(s, qf[0][ks], f2);
                    mma16816(s, qf[1][ks], f1);
                    mma16816(s, qf[2][ks], f0);
                }
            }
        }

        // ---- tail masking (exact FMIN -> p becomes exactly 0) ----
        if (k0 + 64 > n) {
            int cb = 2*(lane & 3);
#pragma unroll
            for (int j = 0; j < 8; j++) {
                int c = k0 + 8*j + cb;
                if (c >= n)     { sf[j][0] = FMIN_F; sf[j][2] = FMIN_F; }
                if (c + 1 >= n) { sf[j][1] = FMIN_F; sf[j][3] = FMIN_F; }
            }
        }

        // ---- online softmax on fragments ----
#pragma unroll
        for (int rh = 0; rh < 2; rh++) {
            float tm = -INFINITY;
#pragma unroll
            for (int j = 0; j < 8; j++)
                tm = fmaxf(tm, fmaxf(sf[j][rh*2], sf[j][rh*2+1]));
            tm = fmaxf(tm, __shfl_xor_sync(0xFFFFFFFFu, tm, 1));
            tm = fmaxf(tm, __shfl_xor_sync(0xFFFFFFFFu, tm, 2));
            float nm = fmaxf(mx[rh], tm);
            float c = __expf(mx[rh] - nm);
            mx[rh] = nm;
            float ps = 0.f;
#pragma unroll
            for (int j = 0; j < 8; j++) {
                float e0 = __expf(sf[j][rh*2]   - nm);
                float e1 = __expf(sf[j][rh*2+1] - nm);
                sf[j][rh*2] = e0; sf[j][rh*2+1] = e1;
                ps += e0 + e1;
            }
            ls[rh] = ls[rh]*c + ps;
#pragma unroll
            for (int nf = 0; nf < 4; nf++) {
                oa[nf][rh*2]   *= c;
                oa[nf][rh*2+1] *= c;
            }
        }

        // ---- O += P V (P RN 3-plane, V RN 2-plane, 5 products) ----
#pragma unroll
        for (int g = 0; g < 4; g++) {
            float* s0 = sf[2*g];
            float* s1 = sf[2*g+1];
            uint16_t t0[8], t1[8], t2[8];
#pragma unroll
            for (int u = 0; u < 4; u++) split3(s0[u], t0[u],   t1[u],   t2[u]);
#pragma unroll
            for (int u = 0; u < 4; u++) split3(s1[u], t0[4+u], t1[4+u], t2[4+u]);
            uint32_t ap0[4], ap1[4], ap2[4];
#pragma unroll
            for (int u = 0; u < 4; u++) {
                ap0[u] = pack16(t0[2*u], t0[2*u+1]);
                ap1[u] = pack16(t1[2*u], t1[2*u+1]);
                ap2[u] = pack16(t2[2*u], t2[2*u+1]);
            }
#pragma unroll
            for (int nb = 0; nb < 2; nb++) {
                uint32_t v0r[4], v1r[4];
                uint32_t voff = vb + (g*16 + (lane & 15))*80 + (nb*16 + (lane >> 4)*8)*2;
                ldsm4t(v0r, voff);
                ldsm4t(v1r, voff + KPLANE);
#pragma unroll
                for (int nj = 0; nj < 2; nj++) {
                    int nf = nb*2 + nj;
                    mma16816(oa[nf], ap0, &v0r[nj*2]);
                    mma16816(oa[nf], ap0, &v1r[nj*2]);
                    mma16816(oa[nf], ap1, &v0r[nj*2]);
                    mma16816(oa[nf], ap1, &v1r[nj*2]);
                    mma16816(oa[nf], ap2, &v0r[nj*2]);
                }
            }
        }
        cur ^= 1;
    }

    // ---- epilogue ----
    float inv[2];
#pragma unroll
    for (int rh = 0; rh < 2; rh++) {
        float l = ls[rh];
        l += __shfl_xor_sync(0xFFFFFFFFu, l, 1);
        l += __shfl_xor_sync(0xFFFFFFFFu, l, 2);
        inv[rh] = 1.f / l;
    }
    int r0 = q0 + wid*16 + (lane >> 2);
    int cb = 2*(lane & 3);
#pragma unroll
    for (int nf = 0; nf < 4; nf++)
#pragma unroll
        for (int rh = 0; rh < 2; rh++) {
            int row = r0 + rh*8;
            float2 val = make_float2(oa[nf][rh*2]*inv[rh], oa[nf][rh*2+1]*inv[rh]);
            *(float2*)(g_o + (size_t)(b*SL + row)*DD + h*32 + 8*nf + cb) = val;
        }
}

// ---------------- fusion reduce: att[tok] = tanh(xWf+bf) . uf ----------------
__global__ void fuse_reduce_kernel(const float* __restrict__ uf)
{
    int wid = threadIdx.x >> 5, lane = threadIdx.x & 31;
    int tok = blockIdx.x*8 + wid;
    int b = tok >> 11, j = tok & 2047;
    if (j >= g_nb[b]) return;
    const float* f = g_ff + (size_t)tok*DD;
    float acc = 0.f;
#pragma unroll
    for (int t = 0; t < 4; t++) {
        int d = lane + t*32;
        acc += f[d] * uf[d];
    }
    acc += __shfl_xor_sync(0xFFFFFFFFu, acc, 16);
    acc += __shfl_xor_sync(0xFFFFFFFFu, acc, 8);
    acc += __shfl_xor_sync(0xFFFFFFFFu, acc, 4);
    acc += __shfl_xor_sync(0xFFFFFFFFu, acc, 2);
    acc += __shfl_xor_sync(0xFFFFFFFFu, acc, 1);
    if (lane == 0) g_att[tok] = acc;
}

// ---------------- masked softmax pooling -------------------------------------
__global__ void pool_kernel()
{
    int b = blockIdx.x;
    int n = g_nb[b];
    int tid = threadIdx.x;
    __shared__ float w[SL];
    __shared__ float red[256];
    float mx = -INFINITY;
    for (int l = tid; l < n; l += 256) mx = fmaxf(mx, g_att[b*SL + l]);
    red[tid] = mx; __syncthreads();
    for (int s = 128; s > 0; s >>= 1) { if (tid < s) red[tid] = fmaxf(red[tid], red[tid+s]); __syncthreads(); }
    mx = red[0]; __syncthreads();
    float sum = 0.f;
    for (int l = tid; l < n; l += 256) { float e = __expf(g_att[b*SL+l] - mx); w[l] = e; sum += e; }
    red[tid] = sum; __syncthreads();
    for (int s = 128; s > 0; s >>= 1) { if (tid < s) red[tid] += red[tid+s]; __syncthreads(); }
    float inv = 1.f / red[0];
    __syncthreads();
    int d = tid & 127, half = tid >> 7;
    float acc = 0.f;
    for (int l = half; l < n; l += 2)
        acc += w[l]*g_x[((size_t)b*SL + l)*DD + d];
    red[tid] = acc; __syncthreads();
    if (tid < 128) g_ts[b*DD + tid] = (red[tid] + red[tid+128])*inv;
}

// ---------------- demographics MLP -------------------------------------------
__global__ void demo_kernel(const float* __restrict__ demo, const float* __restrict__ Wd1,
                            const float* __restrict__ bd1, const float* __restrict__ Wd2,
                            const float* __restrict__ bd2)
{
    int b = blockIdx.x;
    int tid = threadIdx.x;
    __shared__ float ds[DMG];
    __shared__ float hs[256];
    if (tid < DMG) ds[tid] = demo[b*DMG + tid];
    __syncthreads();
    float a = bd1[tid];
#pragma unroll
    for (int k = 0; k < DMG; k++) a += ds[k]*Wd1[k*256 + tid];
    hs[tid] = tanhf(a);
    __syncthreads();
    if (tid < DD) {
        float a2 = bd2[tid];
#pragma unroll 8
        for (int k = 0; k < 256; k++) a2 += hs[k]*Wd2[k*DD + tid];
        g_demo[b*DD + tid] = a2;
    }
}

// ---------------- head --------------------------------------------------------
__global__ void head_kernel(const float* __restrict__ Wh, const float* __restrict__ bh,
                            float* __restrict__ out)
{
    int b = blockIdx.x;
    int tid = threadIdx.x;
    __shared__ float es[256];
    es[tid] = (tid < 128) ? g_ts[b*DD + tid] : g_demo[b*DD + (tid - 128)];
    __syncthreads();
    if (tid < NF) {
        float acc = bh[tid];
#pragma unroll 8
        for (int k = 0; k < 256; k++) acc += es[k]*Wh[k*NF + tid];
        out[b*NF + tid] = acc;
    }
}

// ---------------- orchestration ------------------------------------------------
extern "C" void kernel_launch(void* const* d_in, const int* in_sizes, int n_in,
                              void* d_out, int out_size)
{
    const float* values = (const float*)d_in[0];
    const float* times  = (const float*)d_in[1];
    const int*   vars   = (const int*)d_in[2];
    const void*  maskraw = d_in[3];
    const float* demo   = (const float*)d_in[4];
    const float* W1t = (const float*)d_in[5];
    const float* b1t = (const float*)d_in[6];
    const float* W2t = (const float*)d_in[7];
    const float* W1v = (const float*)d_in[8];
    const float* b1v = (const float*)d_in[9];
    const float* W2v = (const float*)d_in[10];
    const float* vtab = (const float*)d_in[11];
    const float* Wq = (const float*)d_in[12];
    const float* Wk = (const float*)d_in[13];
    const float* Wv = (const float*)d_in[14];
    const float* Wo = (const float*)d_in[15];
    const float* W1 = (const float*)d_in[16];
    const float* b1 = (const float*)d_in[17];
    const float* W2 = (const float*)d_in[18];
    const float* b2 = (const float*)d_in[19];
    const float* Wf = (const float*)d_in[20];
    const float* bf = (const float*)d_in[21];
    const float* uf = (const float*)d_in[22];
    const float* Wd1 = (const float*)d_in[23];
    const float* bd1 = (const float*)d_in[24];
    const float* Wd2 = (const float*)d_in[25];
    const float* bd2 = (const float*)d_in[26];
    const float* Wh = (const float*)d_in[27];
    const float* bh = (const float*)d_in[28];
    float* out = (float*)d_out;

    float *xp, *qkvp, *op, *ffp;
    __nv_bfloat16 *w0p, *w1p, *w2p;
    cudaGetSymbolAddress((void**)&xp,   g_x);
    cudaGetSymbolAddress((void**)&qkvp, g_qkv);
    cudaGetSymbolAddress((void**)&op,   g_o);
    cudaGetSymbolAddress((void**)&ffp,  g_ff);
    cudaGetSymbolAddress((void**)&w0p,  g_wt0);
    cudaGetSymbolAddress((void**)&w1p,  g_wt1);
    cudaGetSymbolAddress((void**)&w2p,  g_wt2);

    cudaFuncSetAttribute(tgemm_kernel, cudaFuncAttributeMaxDynamicSharedMemorySize, TG_SMEM);
    cudaFuncSetAttribute(flash_kernel, cudaFuncAttributeMaxDynamicSharedMemorySize, FL_SMEM);

    mask_reset_kernel<<<1, 32>>>();
    mask_scan_kernel<<<NTOK/4/256, 256>>>((const unsigned int*)maskraw);
    compact_kernel<<<BB, 256>>>(maskraw);

    wrepack_kernel<<<WT_TOTAL/256, 256>>>(Wq, Wk, Wv, Wo, W1, W2, Wf);
    demo_kernel<<<BB, 256>>>(demo, Wd1, bd1, Wd2, bd2);
    embed_kernel<<<NTOK, 128>>>(values, times, vars, W1t, b1t, W2t, W1v, b1v, W2v, vtab);

    for (int i = 0; i < NLAY; i++) {
        const __nv_bfloat16* l0 = w0p + i*WT_LAYER;
        const __nv_bfloat16* l1 = w1p + i*WT_LAYER;
        const __nv_bfloat16* l2 = w2p + i*WT_LAYER;
        // QKV GEMM with fused K/V plane split (epi=5)
        tgemm_kernel<<<dim3(3, NTOK/128), 256, TG_SMEM>>>(xp, l0 + WT_QKV, l1 + WT_QKV, l2 + WT_QKV,
                                                          nullptr, qkvp, 384, 128, 5);
        flash_kernel<<<dim3(SL/128, BB*HH), 256, FL_SMEM>>>();
        tgemm_kernel<<<dim3(1, NTOK/128), 256, TG_SMEM>>>(op, l0 + WT_WO, l1 + WT_WO, l2 + WT_WO,
                                                          nullptr, xp, 128, 128, 1);
        tgemm_kernel<<<dim3(2, NTOK/128), 256, TG_SMEM>>>(xp, l0 + WT_W1, l1 + WT_W1, l2 + WT_W1,
                                                          b1 + i*DFF, ffp, 256, 128, 2);
        tgemm_kernel<<<dim3(1, NTOK/128), 256, TG_SMEM>>>(ffp, l0 + WT_W2, l1 + WT_W2, l2 + WT_W2,
                                                          b2 + i*DD, xp, 128, 256, 3);
    }

    // fusion attention: tanh(x Wf + bf) via split-GEMM, then dot with uf
    tgemm_kernel<<<dim3(1, NTOK/128), 256, TG_SMEM>>>(xp, w0p + WF_OFF, w1p + WF_OFF, w2p + WF_OFF,
                                                      bf, ffp, 128, 128, 4);
    fuse_reduce_kernel<<<NTOK/8, 256>>>(uf);
    pool_kernel<<<BB, 256>>>();
    head_kernel<<<BB, 256>>>(Wh, bh, out);
}

// round 15
// speedup vs baseline: 1.2143x; 1.0722x over previous
#include <cuda_runtime.h>
#include <cuda_bf16.h>
#include <math.h>
#include <stdint.h>

#define BB   16
#define SL   2048
#define DD   128
#define HH   4
#define NLAY 4
#define DKH  32
#define DFF  256
#define NF   129
#define DMG  16
#define INTD 11
#define NTOK (BB*SL)
#define FMIN_F (-3.402823466e38f)

// per-layer transposed bf16 weight planes: qkv[384x128] | wo[128x128] | w1[256x128] | w2[128x256]
#define WT_LAYER 131072
#define WT_QKV   0
#define WT_WO    49152
#define WT_W1    65536
#define WT_W2    98304
#define WF_OFF   (NLAY*WT_LAYER)          // Wf plane appended after layer weights
#define WT_TOTAL (WF_OFF + DD*DD)

// ---------------- scratch (device globals: allocation-free) ----------------
__device__ float g_x[NTOK*DD];
__device__ float g_qkv[NTOK*3*DD];
__device__ float g_o[NTOK*DD];
__device__ float g_ff[NTOK*DFF];
__device__ float g_demo[BB*DD];
__device__ float g_att[BB*SL];
__device__ float g_ts[BB*DD];
__device__ __nv_bfloat16 g_wt0[WT_TOTAL];
__device__ __nv_bfloat16 g_wt1[WT_TOTAL];
__device__ __nv_bfloat16 g_wt2[WT_TOTAL];
// per-(b,h) split planes of K (3) and V (2): [((b*4+h)*SL + j)*32 + e]
#define PL_ELEMS (BB*HH*SL*DKH)
__device__ __nv_bfloat16 g_k0[PL_ELEMS];
__device__ __nv_bfloat16 g_k1[PL_ELEMS];
__device__ __nv_bfloat16 g_k2[PL_ELEMS];
__device__ __nv_bfloat16 g_v0[PL_ELEMS];
__device__ __nv_bfloat16 g_v1[PL_ELEMS];
__device__ int g_idx[NTOK];
__device__ int g_nb[BB];
__device__ int g_npad[BB];
__device__ int g_cnt[2];

// ---------------- PTX helpers -------------------------------------------------
__device__ __forceinline__ uint32_t smem_u32(const void* p) {
    uint32_t a;
    asm("{ .reg .u64 t; cvta.to.shared.u64 t, %1; cvt.u32.u64 %0, t; }" : "=r"(a) : "l"(p));
    return a;
}
__device__ __forceinline__ void ldsm4(uint32_t* r, uint32_t addr) {
    asm volatile("ldmatrix.sync.aligned.m8n8.x4.shared.b16 {%0,%1,%2,%3}, [%4];"
        : "=r"(r[0]), "=r"(r[1]), "=r"(r[2]), "=r"(r[3]) : "r"(addr));
}
__device__ __forceinline__ void ldsm4t(uint32_t* r, uint32_t addr) {
    asm volatile("ldmatrix.sync.aligned.m8n8.x4.trans.shared.b16 {%0,%1,%2,%3}, [%4];"
        : "=r"(r[0]), "=r"(r[1]), "=r"(r[2]), "=r"(r[3]) : "r"(addr));
}
__device__ __forceinline__ void mma16816(float* d, const uint32_t* a, const uint32_t* b) {
    asm volatile("mma.sync.aligned.m16n8k16.row.col.f32.bf16.bf16.f32 "
        "{%0,%1,%2,%3}, {%4,%5,%6,%7}, {%8,%9}, {%0,%1,%2,%3};"
        : "+f"(d[0]), "+f"(d[1]), "+f"(d[2]), "+f"(d[3])
        : "r"(a[0]), "r"(a[1]), "r"(a[2]), "r"(a[3]), "r"(b[0]), "r"(b[1]));
}
// scalar RN 3-way split (setup kernels only)
__device__ __forceinline__ void split3(float x, uint16_t& h0, uint16_t& h1, uint16_t& h2) {
    __nv_bfloat16 b0 = __float2bfloat16(x);
    float r1 = x - __bfloat162float(b0);
    __nv_bfloat16 b1 = __float2bfloat16(r1);
    float r2 = r1 - __bfloat162float(b1);
    __nv_bfloat16 b2 = __float2bfloat16(r2);
    h0 = __bfloat16_as_ushort(b0);
    h1 = __bfloat16_as_ushort(b1);
    h2 = __bfloat16_as_ushort(b2);
}
// paired RN 3-way split: q0/q1/q2 pack (lo=split(a), hi=split(b)) per plane.
// cvt.rn.bf16x2.f32 uses the same RN rounding as __float2bfloat16; bf16bits<<16
// reconstructs the exact fp32 value -> bit-identical to 2x split3 + pack16.
__device__ __forceinline__ void split3x2(float a, float b,
                                         uint32_t& q0, uint32_t& q1, uint32_t& q2) {
    asm("cvt.rn.bf16x2.f32 %0, %1, %2;" : "=r"(q0) : "f"(b), "f"(a));
    float ra = a - __uint_as_float(q0 << 16);
    float rb = b - __uint_as_float(q0 & 0xFFFF0000u);
    asm("cvt.rn.bf16x2.f32 %0, %1, %2;" : "=r"(q1) : "f"(rb), "f"(ra));
    float ra2 = ra - __uint_as_float(q1 << 16);
    float rb2 = rb - __uint_as_float(q1 & 0xFFFF0000u);
    asm("cvt.rn.bf16x2.f32 %0, %1, %2;" : "=r"(q2) : "f"(rb2), "f"(ra2));
}
__device__ __forceinline__ void split2x2(float a, float b, uint32_t& q0, uint32_t& q1) {
    asm("cvt.rn.bf16x2.f32 %0, %1, %2;" : "=r"(q0) : "f"(b), "f"(a));
    float ra = a - __uint_as_float(q0 << 16);
    float rb = b - __uint_as_float(q0 & 0xFFFF0000u);
    asm("cvt.rn.bf16x2.f32 %0, %1, %2;" : "=r"(q1) : "f"(rb), "f"(ra));
}

// ---------------- mask dtype detection ---------------------------------------
__global__ void mask_reset_kernel() {
    if (threadIdx.x < 2) g_cnt[threadIdx.x] = 0;
}
__global__ void mask_scan_kernel(const unsigned int* __restrict__ w) {
    int i = blockIdx.x*256 + threadIdx.x;
    unsigned int v = w[i];
    if (v > 1u) atomicOr(&g_cnt[0], 1);
    if (v != 0u && v != 0x3F800000u) atomicOr(&g_cnt[1], 1);
}

// ---------------- stable compaction (dtype dispatch fused) -------------------
__global__ void compact_kernel(const void* __restrict__ p)
{
    int b = blockIdx.x, tid = threadIdx.x;
    __shared__ int sc[256];
    __shared__ int sbase;
    int mode = (g_cnt[0] == 0) ? 0 : (g_cnt[1] == 0) ? 1 : 2;
    if (tid == 0) sbase = 0;
    __syncthreads();
    for (int c = 0; c < SL; c += 256) {
        int l = c + tid;
        int m;
        if (mode == 0)      m = ((const int*)p)[b*SL + l] != 0;
        else if (mode == 1) m = ((const float*)p)[b*SL + l] != 0.0f;
        else                m = ((const unsigned char*)p)[b*SL + l] != 0;
        sc[tid] = m;
        __syncthreads();
#pragma unroll
        for (int s = 1; s < 256; s <<= 1) {
            int v = (tid >= s) ? sc[tid - s] : 0;
            __syncthreads();
            sc[tid] += v;
            __syncthreads();
        }
        int pos = sbase + sc[tid] - m;
        if (m) g_idx[b*SL + pos] = l;
        int tot = sc[255];
        __syncthreads();
        if (tid == 0) sbase += tot;
        __syncthreads();
    }
    if (tid == 0) { g_nb[b] = sbase; g_npad[b] = (sbase + 127) & ~127; }
}

// ---------------- embedding (compacted) --------------------------------------
__global__ void embed_kernel(const float* __restrict__ values, const float* __restrict__ times,
                             const int* __restrict__ vars,
                             const float* __restrict__ W1t, const float* __restrict__ b1t,
                             const float* __restrict__ W2t,
                             const float* __restrict__ W1v, const float* __restrict__ b1v,
                             const float* __restrict__ W2v,
                             const float* __restrict__ vtab)
{
    int tok = blockIdx.x;
    int b = tok >> 11, j = tok & 2047;
    int d = threadIdx.x;
    if (j >= g_npad[b]) return;
    if (j >= g_nb[b]) { g_x[(size_t)tok*DD + d] = 0.f; return; }
    int l = g_idx[tok];
    __shared__ float tt[INTD], vv[INTD];
    if (d < INTD) {
        float t = times[b*SL + l], v = values[b*SL + l];
        tt[d] = tanhf(t * W1t[d] + b1t[d]);
        vv[d] = tanhf(v * W1v[d] + b1v[d]);
    }
    __syncthreads();
    int var = vars[b*SL + l];
    float acc = vtab[var*DD + d];
#pragma unroll
    for (int i = 0; i < INTD; i++)
        acc += tt[i]*W2t[i*DD+d] + vv[i]*W2v[i*DD+d];
    g_x[(size_t)tok*DD + d] = acc;
}

// ---------------- weight repack: transpose + bf16 3-way split ----------------
__global__ void wrepack_kernel(const float* __restrict__ Wq, const float* __restrict__ Wk,
                               const float* __restrict__ Wv, const float* __restrict__ Wo,
                               const float* __restrict__ W1, const float* __restrict__ W2,
                               const float* __restrict__ Wf)
{
    int idx = blockIdx.x*256 + threadIdx.x;      // < WT_TOTAL
    float v;
    if (idx >= WF_OFF) {             // fusion Wf: [dout][din] transposed
        int rr = idx - WF_OFF;
        int n = rr >> 7, k = rr & 127;
        v = Wf[k*DD + n];
    } else {
        int layer = idx >> 17;
        int r = idx & (WT_LAYER-1);
        if (r < WT_WO) {                 // qkv: n = sel*128+h*32+e, k = d
            int n = r >> 7, k = r & 127;
            int sel = n >> 7;
            int he = n & 127, h = he >> 5, e = he & 31;
            const float* W = sel == 0 ? Wq : (sel == 1 ? Wk : Wv);
            v = W[layer*HH*DD*DKH + h*DD*DKH + k*DKH + e];
        } else if (r < WT_W1) {          // wo: [dout][din]
            int rr = r - WT_WO; int n = rr >> 7, k = rr & 127;
            v = Wo[layer*DD*DD + k*DD + n];
        } else if (r < WT_W2) {          // w1: [f][d]
            int rr = r - WT_W1; int n = rr >> 7, k = rr & 127;
            v = W1[layer*DD*DFF + k*DFF + n];
        } else {                         // w2: [d][f]
            int rr = r - WT_W2; int n = rr >> 8, k = rr & 255;
            v = W2[layer*DFF*DD + k*DD + n];
        }
    }
    uint16_t h0, h1, h2;
    split3(v, h0, h1, h2);
    g_wt0[idx] = __ushort_as_bfloat16(h0);
    g_wt1[idx] = __ushort_as_bfloat16(h1);
    g_wt2[idx] = __ushort_as_bfloat16(h2);
}

// ---------------- HMMA 3-way-split GEMM: C tile 128x128 ----------------------
// epi: 0 none | 1 +=C | 2 bias+gelu | 3 bias+ +=C | 4 bias+tanh | 5 qkv (q->C, k/v->split planes)
#define PLANE 10240                        // 128 rows * 40 cols * 2B (tgemm planes)
#define TG_SMEM (6*PLANE)

__global__ __launch_bounds__(256)
void tgemm_kernel(const float* __restrict__ A,
                  const __nv_bfloat16* __restrict__ B0,
                  const __nv_bfloat16* __restrict__ B1,
                  const __nv_bfloat16* __restrict__ B2,
                  const float* __restrict__ bias,
                  float* __restrict__ C, int N, int K, int epi)
{
    int bm = blockIdx.y * 128;
    if ((bm & 2047) >= g_npad[bm >> 11]) return;
    int bn = blockIdx.x * 128;

    extern __shared__ char smem[];
    uint16_t (*sA0)[40] = (uint16_t(*)[40])(smem);
    uint16_t (*sA1)[40] = (uint16_t(*)[40])(smem + PLANE);
    uint16_t (*sA2)[40] = (uint16_t(*)[40])(smem + 2*PLANE);
    uint16_t (*sB0)[40] = (uint16_t(*)[40])(smem + 3*PLANE);
    uint16_t (*sB1)[40] = (uint16_t(*)[40])(smem + 4*PLANE);
    uint16_t (*sB2)[40] = (uint16_t(*)[40])(smem + 5*PLANE);

    int tid = threadIdx.x, wid = tid >> 5, lane = tid & 31;
    int wm = (wid & 3) * 32, wn = (wid >> 2) * 64;

    float acc[2][8][4];
#pragma unroll
    for (int mi = 0; mi < 2; mi++)
#pragma unroll
        for (int ni = 0; ni < 8; ni++)
#pragma unroll
            for (int c = 0; c < 4; c++) acc[mi][ni][c] = 0.f;

    uint32_t bA0 = smem_u32(sA0), bA1 = smem_u32(sA1), bA2 = smem_u32(sA2);
    uint32_t bB0 = smem_u32(sB0), bB1 = smem_u32(sB1), bB2 = smem_u32(sB2);
    int rowA = lane & 15, colA8 = (lane >> 4) * 8;
    int rowB = ((lane >> 4) << 3) + (lane & 7), colB8 = ((lane >> 3) & 1) * 8;

    int arow = tid >> 3, ac4 = (tid & 7) * 4;    // staging coords (4 iters of 256)
    // prologue: prefetch A k-tile 0 into registers
    float4 areg[4];
#pragma unroll
    for (int it = 0; it < 4; it++) {
        int row = arow + it*32;
        areg[it] = *(const float4*)(A + (size_t)(bm + row)*K + ac4);
    }

    for (int k0 = 0; k0 < K; k0 += 32) {
        // stage A from prefetched regs (paired split), B as plane copies
#pragma unroll
        for (int it = 0; it < 4; it++) {
            int row = arow + it*32;
            float4 a = areg[it];
            uint32_t q00, q01, q02, q10, q11, q12;
            split3x2(a.x, a.y, q00, q01, q02);
            split3x2(a.z, a.w, q10, q11, q12);
            *(uint2*)&sA0[row][ac4] = make_uint2(q00, q10);
            *(uint2*)&sA1[row][ac4] = make_uint2(q01, q11);
            *(uint2*)&sA2[row][ac4] = make_uint2(q02, q12);
        }
#pragma unroll
        for (int it = 0; it < 4; it++) {
            int row = arow + it*32;
            size_t goff = (size_t)(bn + row)*K + k0 + ac4;
            *(uint2*)&sB0[row][ac4] = *(const uint2*)(B0 + goff);
            *(uint2*)&sB1[row][ac4] = *(const uint2*)(B1 + goff);
            *(uint2*)&sB2[row][ac4] = *(const uint2*)(B2 + goff);
        }
        __syncthreads();

        // prefetch next A k-tile (LDG latency hides under the MMA phase)
        if (k0 + 32 < K) {
#pragma unroll
            for (int it = 0; it < 4; it++) {
                int row = arow + it*32;
                areg[it] = *(const float4*)(A + (size_t)(bm + row)*K + k0 + 32 + ac4);
            }
        }

#pragma unroll
        for (int ks = 0; ks < 32; ks += 16) {
            uint32_t a0[2][4], a1[2][4], a2[2][4];
#pragma unroll
            for (int mi = 0; mi < 2; mi++) {
                uint32_t off = ((uint32_t)((wm + mi*16 + rowA)*40 + ks + colA8)) * 2;
                ldsm4(a0[mi], bA0 + off);
                ldsm4(a1[mi], bA1 + off);
                ldsm4(a2[mi], bA2 + off);
            }
#pragma unroll
            for (int pi = 0; pi < 4; pi++) {
                uint32_t off = ((uint32_t)((wn + pi*16 + rowB)*40 + ks + colB8)) * 2;
                uint32_t b0[4], b1[4], b2[4];
                ldsm4(b0, bB0 + off);
                ldsm4(b1, bB1 + off);
                ldsm4(b2, bB2 + off);
#pragma unroll
                for (int mi = 0; mi < 2; mi++)
#pragma unroll
                    for (int nj = 0; nj < 2; nj++) {
                        float* ac = acc[mi][pi*2 + nj];
                        const uint32_t* f0 = &b0[nj*2];
                        const uint32_t* f1 = &b1[nj*2];
                        const uint32_t* f2 = &b2[nj*2];
                        mma16816(ac, a0[mi], f0);
                        mma16816(ac, a0[mi], f1);
                        mma16816(ac, a1[mi], f0);
                        mma16816(ac, a0[mi], f2);
                        mma16816(ac, a1[mi], f1);
                        mma16816(ac, a2[mi], f0);
                    }
            }
        }
        __syncthreads();
    }

    int r0base = bm + wm + (lane >> 2);
    int cbase = wn + (lane & 3) * 2;
#pragma unroll
    for (int mi = 0; mi < 2; mi++) {
#pragma unroll
        for (int ni = 0; ni < 8; ni++) {
            int col = bn + cbase + ni*8;
#pragma unroll
            for (int half = 0; half < 2; half++) {
                int row = r0base + mi*16 + half*8;
                float v0 = acc[mi][ni][half*2], v1 = acc[mi][ni][half*2+1];
                if (epi == 5) {
                    if (col < 128) {
                        *(float2*)(C + (size_t)row*N + col) = make_float2(v0, v1);
                    } else {
                        int cc = col - 128;
                        int sel = cc >> 7;
                        int hh = (cc >> 5) & 3;
                        int e  = cc & 31;
                        int bb = row >> 11, jj = row & 2047;
                        size_t dst = ((size_t)(bb*4 + hh)*SL + jj)*32 + e;
                        if (sel == 0) {
                            uint32_t w0, w1, w2;
                            split3x2(v0, v1, w0, w1, w2);
                            *(uint32_t*)(g_k0 + dst) = w0;
                            *(uint32_t*)(g_k1 + dst) = w1;
                            *(uint32_t*)(g_k2 + dst) = w2;
                        } else {
                            uint32_t w0, w1;
                            split2x2(v0, v1, w0, w1);
                            *(uint32_t*)(g_v0 + dst) = w0;
                            *(uint32_t*)(g_v1 + dst) = w1;
                        }
                    }
                    continue;
                }
                float* Cp = C + (size_t)row*N + col;
                if (epi >= 2) {
                    v0 += bias[col]; v1 += bias[col+1];
                }
                if (epi == 2) {
                    v0 = 0.5f*v0*(1.f + erff(v0*0.7071067811865476f));
                    v1 = 0.5f*v1*(1.f + erff(v1*0.7071067811865476f));
                }
                if (epi == 4) {
                    v0 = tanhf(v0);
                    v1 = tanhf(v1);
                }
                if (epi == 1 || epi == 3) {
                    float2 o = *(const float2*)Cp;
                    v0 += o.x; v1 += o.y;
                }
                *(float2*)Cp = make_float2(v0, v1);
            }
        }
    }
}

// ---------------- HMMA flash attention ---------------------------------------
// block: 8 warps, 128 queries x one (b,h); key tiles of 64, cp.async double-buffered
#define KPLANE 5120                  // one [64][40] uint16 KV plane
#define QPLANE 10240                 // one [128][40] uint16 Q plane
#define FL_SQ   0
#define FL_BUF  (3*QPLANE)           // 30720
#define FL_BUFSZ (5*KPLANE)          // K0 K1 K2 V0 V1 = 25600
#define FL_SMEM (FL_BUF + 2*FL_BUFSZ)  // 81920

__device__ __forceinline__ void stage_kv_async(uint32_t dstb, int bh, int k0, int tid)
{
#pragma unroll
    for (int it = 0; it < 5; it++) {
        int idx = tid + it*256;             // 1280 uint4
        int plane = idx >> 8;               // 0..4
        int r = (idx >> 2) & 63;
        int e8 = (idx & 3) * 8;
        const __nv_bfloat16* src =
            plane == 0 ? g_k0 : plane == 1 ? g_k1 : plane == 2 ? g_k2 :
            plane == 3 ? g_v0 : g_v1;
        const void* gptr = src + ((size_t)bh*SL + k0 + r)*32 + e8;
        uint32_t dst = dstb + plane*KPLANE + r*80 + e8*2;
        asm volatile("cp.async.cg.shared.global [%0], [%1], 16;"
                     :: "r"(dst), "l"(gptr) : "memory");
    }
    asm volatile("cp.async.commit_group;" ::: "memory");
}

__global__ __launch_bounds__(256)
void flash_kernel()
{
    extern __shared__ char fsm[];
    int bh = blockIdx.y;
    int b = bh >> 2, h = bh & 3;
    int n = g_nb[b];
    int q0 = blockIdx.x * 128;
    if (q0 >= n) return;

    int tid = threadIdx.x, wid = tid >> 5, lane = tid & 31;
    uint32_t sbase = smem_u32(fsm);

    // ---- stage Q (fp32 -> RN 3-plane split, paired cvt), 128 rows ----
#pragma unroll
    for (int it = 0; it < 4; it++) {
        int idx = tid + it*256;                 // 1024 float4-groups
        int row = idx >> 3, c4 = (idx & 7) * 4;
        float4 f = *(const float4*)(g_qkv + (size_t)(b*SL + q0 + row)*384 + h*32 + c4);
        uint32_t q00, q01, q02, q10, q11, q12;
        split3x2(f.x, f.y, q00, q01, q02);
        split3x2(f.z, f.w, q10, q11, q12);
        *(uint2*)(fsm + FL_SQ + 0*QPLANE + row*80 + c4*2) = make_uint2(q00, q10);
        *(uint2*)(fsm + FL_SQ + 1*QPLANE + row*80 + c4*2) = make_uint2(q01, q11);
        *(uint2*)(fsm + FL_SQ + 2*QPLANE + row*80 + c4*2) = make_uint2(q02, q12);
    }
    __syncthreads();

    // Q fragments held in registers for the whole kernel (warp wid owns rows wid*16..+16)
    uint32_t qf[3][2][4];
    int rowA = lane & 15, colA8 = (lane >> 4) * 8;
#pragma unroll
    for (int p = 0; p < 3; p++)
#pragma unroll
        for (int ks = 0; ks < 2; ks++)
            ldsm4(qf[p][ks], sbase + FL_SQ + p*QPLANE + (wid*16 + rowA)*80 + (ks*16 + colA8)*2);

    float mx[2] = {-INFINITY, -INFINITY};
    float ls[2] = {0.f, 0.f};
    float oa[4][4];
#pragma unroll
    for (int i = 0; i < 4; i++)
#pragma unroll
        for (int u = 0; u < 4; u++) oa[i][u] = 0.f;

    int rowB = ((lane >> 4) << 3) + (lane & 7), colB8 = ((lane >> 3) & 1) * 8;

    int nt = (n + 63) >> 6;
    uint32_t bufb[2] = { sbase + FL_BUF, sbase + FL_BUF + FL_BUFSZ };
    stage_kv_async(bufb[0], bh, 0, tid);
    int cur = 0;

    for (int t = 0; t < nt; t++) {
        int k0 = t*64;
        asm volatile("cp.async.wait_group 0;" ::: "memory");
        __syncthreads();
        if (t + 1 < nt) stage_kv_async(bufb[cur ^ 1], bh, k0 + 64, tid);
        uint32_t kb = bufb[cur];
        uint32_t vb = bufb[cur] + 3*KPLANE;

        // ---- S = Q K^T (6-product RN split) ----
        float sf[8][4];
#pragma unroll
        for (int j = 0; j < 8; j++)
#pragma unroll
            for (int u = 0; u < 4; u++) sf[j][u] = 0.f;

#pragma unroll
        for (int ks = 0; ks < 2; ks++) {
#pragma unroll
            for (int i = 0; i < 4; i++) {       // n16 key groups
                uint32_t off0 = kb + (i*16 + rowB)*80 + (ks*16 + colB8)*2;
                uint32_t kb0[4], kb1[4], kb2[4];
                ldsm4(kb0, off0);
                ldsm4(kb1, off0 + KPLANE);
                ldsm4(kb2, off0 + 2*KPLANE);
#pragma unroll
                for (int nj = 0; nj < 2; nj++) {
                    float* s = sf[i*2 + nj];
                    const uint32_t* f0 = &kb0[nj*2];
                    const uint32_t* f1 = &kb1[nj*2];
                    const uint32_t* f2 = &kb2[nj*2];
                    mma16816(s, qf[0][ks], f0);
                    mma16816(s, qf[0][ks], f1);
                    mma16816(s, qf[1][ks], f0);
                    mma16816(s, qf[0][ks], f2);
                    mma16816(s, qf[1][ks], f1);
                    mma16816(s, qf[2][ks], f0);
                }
            }
        }

        // ---- tail masking (exact FMIN -> p becomes exactly 0) ----
        if (k0 + 64 > n) {
            int cb = 2*(lane & 3);
#pragma unroll
            for (int j = 0; j < 8; j++) {
                int c = k0 + 8*j + cb;
                if (c >= n)     { sf[j][0] = FMIN_F; sf[j][2] = FMIN_F; }
                if (c + 1 >= n) { sf[j][1] = FMIN_F; sf[j][3] = FMIN_F; }
            }
        }

        // ---- online softmax on fragments ----
#pragma unroll
        for (int rh = 0; rh < 2; rh++) {
            float tm = -INFINITY;
#pragma unroll
            for (int j = 0; j < 8; j++)
                tm = fmaxf(tm, fmaxf(sf[j][rh*2], sf[j][rh*2+1]));
            tm = fmaxf(tm, __shfl_xor_sync(0xFFFFFFFFu, tm, 1));
            tm = fmaxf(tm, __shfl_xor_sync(0xFFFFFFFFu, tm, 2));
            float nm = fmaxf(mx[rh], tm);
            float c = __expf(mx[rh] - nm);
            mx[rh] = nm;
            float ps = 0.f;
#pragma unroll
            for (int j = 0; j < 8; j++) {
                float e0 = __expf(sf[j][rh*2]   - nm);
                float e1 = __expf(sf[j][rh*2+1] - nm);
                sf[j][rh*2] = e0; sf[j][rh*2+1] = e1;
                ps += e0 + e1;
            }
            ls[rh] = ls[rh]*c + ps;
#pragma unroll
            for (int nf = 0; nf < 4; nf++) {
                oa[nf][rh*2]   *= c;
                oa[nf][rh*2+1] *= c;
            }
        }

        // ---- O += P V (P RN 3-plane paired split, V RN 2-plane, 5 products) ----
#pragma unroll
        for (int g = 0; g < 4; g++) {
            float* s0 = sf[2*g];
            float* s1 = sf[2*g+1];
            uint32_t ap0[4], ap1[4], ap2[4];
            split3x2(s0[0], s0[1], ap0[0], ap1[0], ap2[0]);
            split3x2(s0[2], s0[3], ap0[1], ap1[1], ap2[1]);
            split3x2(s1[0], s1[1], ap0[2], ap1[2], ap2[2]);
            split3x2(s1[2], s1[3], ap0[3], ap1[3], ap2[3]);
#pragma unroll
            for (int nb = 0; nb < 2; nb++) {
                uint32_t v0r[4], v1r[4];
                uint32_t voff = vb + (g*16 + (lane & 15))*80 + (nb*16 + (lane >> 4)*8)*2;
                ldsm4t(v0r, voff);
                ldsm4t(v1r, voff + KPLANE);
#pragma unroll
                for (int nj = 0; nj < 2; nj++) {
                    int nf = nb*2 + nj;
                    mma16816(oa[nf], ap0, &v0r[nj*2]);
                    mma16816(oa[nf], ap0, &v1r[nj*2]);
                    mma16816(oa[nf], ap1, &v0r[nj*2]);
                    mma16816(oa[nf], ap1, &v1r[nj*2]);
                    mma16816(oa[nf], ap2, &v0r[nj*2]);
                }
            }
        }
        cur ^= 1;
    }

    // ---- epilogue ----
    float inv[2];
#pragma unroll
    for (int rh = 0; rh < 2; rh++) {
        float l = ls[rh];
        l += __shfl_xor_sync(0xFFFFFFFFu, l, 1);
        l += __shfl_xor_sync(0xFFFFFFFFu, l, 2);
        inv[rh] = 1.f / l;
    }
    int r0 = q0 + wid*16 + (lane >> 2);
    int cb = 2*(lane & 3);
#pragma unroll
    for (int nf = 0; nf < 4; nf++)
#pragma unroll
        for (int rh = 0; rh < 2; rh++) {
            int row = r0 + rh*8;
            float2 val = make_float2(oa[nf][rh*2]*inv[rh], oa[nf][rh*2+1]*inv[rh]);
            *(float2*)(g_o + (size_t)(b*SL + row)*DD + h*32 + 8*nf + cb) = val;
        }
}

// ---------------- fusion reduce: att[tok] = tanh(xWf+bf) . uf ----------------
__global__ void fuse_reduce_kernel(const float* __restrict__ uf)
{
    int wid = threadIdx.x >> 5, lane = threadIdx.x & 31;
    int tok = blockIdx.x*8 + wid;
    int b = tok >> 11, j = tok & 2047;
    if (j >= g_nb[b]) return;
    const float* f = g_ff + (size_t)tok*DD;
    float acc = 0.f;
#pragma unroll
    for (int t = 0; t < 4; t++) {
        int d = lane + t*32;
        acc += f[d] * uf[d];
    }
    acc += __shfl_xor_sync(0xFFFFFFFFu, acc, 16);
    acc += __shfl_xor_sync(0xFFFFFFFFu, acc, 8);
    acc += __shfl_xor_sync(0xFFFFFFFFu, acc, 4);
    acc += __shfl_xor_sync(0xFFFFFFFFu, acc, 2);
    acc += __shfl_xor_sync(0xFFFFFFFFu, acc, 1);
    if (lane == 0) g_att[tok] = acc;
}

// ---------------- masked softmax pooling -------------------------------------
__global__ void pool_kernel()
{
    int b = blockIdx.x;
    int n = g_nb[b];
    int tid = threadIdx.x;
    __shared__ float w[SL];
    __shared__ float red[256];
    float mx = -INFINITY;
    for (int l = tid; l < n; l += 256) mx = fmaxf(mx, g_att[b*SL + l]);
    red[tid] = mx; __syncthreads();
    for (int s = 128; s > 0; s >>= 1) { if (tid < s) red[tid] = fmaxf(red[tid], red[tid+s]); __syncthreads(); }
    mx = red[0]; __syncthreads();
    float sum = 0.f;
    for (int l = tid; l < n; l += 256) { float e = __expf(g_att[b*SL+l] - mx); w[l] = e; sum += e; }
    red[tid] = sum; __syncthreads();
    for (int s = 128; s > 0; s >>= 1) { if (tid < s) red[tid] += red[tid+s]; __syncthreads(); }
    float inv = 1.f / red[0];
    __syncthreads();
    int d = tid & 127, half = tid >> 7;
    float acc = 0.f;
    for (int l = half; l < n; l += 2)
        acc += w[l]*g_x[((size_t)b*SL + l)*DD + d];
    red[tid] = acc; __syncthreads();
    if (tid < 128) g_ts[b*DD + tid] = (red[tid] + red[tid+128])*inv;
}

// ---------------- demographics MLP -------------------------------------------
__global__ void demo_kernel(const float* __restrict__ demo, const float* __restrict__ Wd1,
                            const float* __restrict__ bd1, const float* __restrict__ Wd2,
                            const float* __restrict__ bd2)
{
    int b = blockIdx.x;
    int tid = threadIdx.x;
    __shared__ float ds[DMG];
    __shared__ float hs[256];
    if (tid < DMG) ds[tid] = demo[b*DMG + tid];
    __syncthreads();
    float a = bd1[tid];
#pragma unroll
    for (int k = 0; k < DMG; k++) a += ds[k]*Wd1[k*256 + tid];
    hs[tid] = tanhf(a);
    __syncthreads();
    if (tid < DD) {
        float a2 = bd2[tid];
#pragma unroll 8
        for (int k = 0; k < 256; k++) a2 += hs[k]*Wd2[k*DD + tid];
        g_demo[b*DD + tid] = a2;
    }
}

// ---------------- head --------------------------------------------------------
__global__ void head_kernel(const float* __restrict__ Wh, const float* __restrict__ bh,
                            float* __restrict__ out)
{
    int b = blockIdx.x;
    int tid = threadIdx.x;
    __shared__ float es[256];
    es[tid] = (tid < 128) ? g_ts[b*DD + tid] : g_demo[b*DD + (tid - 128)];
    __syncthreads();
    if (tid < NF) {
        float acc = bh[tid];
#pragma unroll 8
        for (int k = 0; k < 256; k++) acc += es[k]*Wh[k*NF + tid];
        out[b*NF + tid] = acc;
    }
}

// ---------------- orchestration ------------------------------------------------
extern "C" void kernel_launch(void* const* d_in, const int* in_sizes, int n_in,
                              void* d_out, int out_size)
{
    const float* values = (const float*)d_in[0];
    const float* times  = (const float*)d_in[1];
    const int*   vars   = (const int*)d_in[2];
    const void*  maskraw = d_in[3];
    const float* demo   = (const float*)d_in[4];
    const float* W1t = (const float*)d_in[5];
    const float* b1t = (const float*)d_in[6];
    const float* W2t = (const float*)d_in[7];
    const float* W1v = (const float*)d_in[8];
    const float* b1v = (const float*)d_in[9];
    const float* W2v = (const float*)d_in[10];
    const float* vtab = (const float*)d_in[11];
    const float* Wq = (const float*)d_in[12];
    const float* Wk = (const float*)d_in[13];
    const float* Wv = (const float*)d_in[14];
    const float* Wo = (const float*)d_in[15];
    const float* W1 = (const float*)d_in[16];
    const float* b1 = (const float*)d_in[17];
    const float* W2 = (const float*)d_in[18];
    const float* b2 = (const float*)d_in[19];
    const float* Wf = (const float*)d_in[20];
    const float* bf = (const float*)d_in[21];
    const float* uf = (const float*)d_in[22];
    const float* Wd1 = (const float*)d_in[23];
    const float* bd1 = (const float*)d_in[24];
    const float* Wd2 = (const float*)d_in[25];
    const float* bd2 = (const float*)d_in[26];
    const float* Wh = (const float*)d_in[27];
    const float* bh = (const float*)d_in[28];
    float* out = (float*)d_out;

    float *xp, *qkvp, *op, *ffp;
    __nv_bfloat16 *w0p, *w1p, *w2p;
    cudaGetSymbolAddress((void**)&xp,   g_x);
    cudaGetSymbolAddress((void**)&qkvp, g_qkv);
    cudaGetSymbolAddress((void**)&op,   g_o);
    cudaGetSymbolAddress((void**)&ffp,  g_ff);
    cudaGetSymbolAddress((void**)&w0p,  g_wt0);
    cudaGetSymbolAddress((void**)&w1p,  g_wt1);
    cudaGetSymbolAddress((void**)&w2p,  g_wt2);

    cudaFuncSetAttribute(tgemm_kernel, cudaFuncAttributeMaxDynamicSharedMemorySize, TG_SMEM);
    cudaFuncSetAttribute(flash_kernel, cudaFuncAttributeMaxDynamicSharedMemorySize, FL_SMEM);

    mask_reset_kernel<<<1, 32>>>();
    mask_scan_kernel<<<NTOK/4/256, 256>>>((const unsigned int*)maskraw);
    compact_kernel<<<BB, 256>>>(maskraw);

    wrepack_kernel<<<WT_TOTAL/256, 256>>>(Wq, Wk, Wv, Wo, W1, W2, Wf);
    demo_kernel<<<BB, 256>>>(demo, Wd1, bd1, Wd2, bd2);
    embed_kernel<<<NTOK, 128>>>(values, times, vars, W1t, b1t, W2t, W1v, b1v, W2v, vtab);

    for (int i = 0; i < NLAY; i++) {
        const __nv_bfloat16* l0 = w0p + i*WT_LAYER;
        const __nv_bfloat16* l1 = w1p + i*WT_LAYER;
        const __nv_bfloat16* l2 = w2p + i*WT_LAYER;
        // QKV GEMM with fused K/V plane split (epi=5)
        tgemm_kernel<<<dim3(3, NTOK/128), 256, TG_SMEM>>>(xp, l0 + WT_QKV, l1 + WT_QKV, l2 + WT_QKV,
                                                          nullptr, qkvp, 384, 128, 5);
        flash_kernel<<<dim3(SL/128, BB*HH), 256, FL_SMEM>>>();
        tgemm_kernel<<<dim3(1, NTOK/128), 256, TG_SMEM>>>(op, l0 + WT_WO, l1 + WT_WO, l2 + WT_WO,
                                                          nullptr, xp, 128, 128, 1);
        tgemm_kernel<<<dim3(2, NTOK/128), 256, TG_SMEM>>>(xp, l0 + WT_W1, l1 + WT_W1, l2 + WT_W1,
                                                          b1 + i*DFF, ffp, 256, 128, 2);
        tgemm_kernel<<<dim3(1, NTOK/128), 256, TG_SMEM>>>(ffp, l0 + WT_W2, l1 + WT_W2, l2 + WT_W2,
                                                          b2 + i*DD, xp, 128, 256, 3);
    }

    // fusion attention: tanh(x Wf + bf) via split-GEMM, then dot with uf
    tgemm_kernel<<<dim3(1, NTOK/128), 256, TG_SMEM>>>(xp, w0p + WF_OFF, w1p + WF_OFF, w2p + WF_OFF,
                                                      bf, ffp, 128, 128, 4);
    fuse_reduce_kernel<<<NTOK/8, 256>>>(uf);
    pool_kernel<<<BB, 256>>>();
    head_kernel<<<BB, 256>>>(Wh, bh, out);
}

// round 16
// speedup vs baseline: 1.2203x; 1.0049x over previous
#include <cuda_runtime.h>
#include <cuda_bf16.h>
#include <math.h>
#include <stdint.h>

#define BB   16
#define SL   2048
#define DD   128
#define HH   4
#define NLAY 4
#define DKH  32
#define DFF  256
#define NF   129
#define DMG  16
#define INTD 11
#define NTOK (BB*SL)
#define FMIN_F (-3.402823466e38f)

// per-layer transposed bf16 weight planes: qkv[384x128] | wo[128x128] | w1[256x128] | w2[128x256]
#define WT_LAYER 131072
#define WT_QKV   0
#define WT_WO    49152
#define WT_W1    65536
#define WT_W2    98304
#define WF_OFF   (NLAY*WT_LAYER)          // Wf plane appended after layer weights
#define WT_TOTAL (WF_OFF + DD*DD)

// ---------------- scratch (device globals: allocation-free) ----------------
__device__ float g_x[NTOK*DD];
__device__ float g_qkv[NTOK*3*DD];
__device__ float g_o[NTOK*DD];
__device__ float g_ff[NTOK*DFF];
__device__ float g_demo[BB*DD];
__device__ float g_att[BB*SL];
__device__ float g_ts[BB*DD];
__device__ __nv_bfloat16 g_wt0[WT_TOTAL];
__device__ __nv_bfloat16 g_wt1[WT_TOTAL];
__device__ __nv_bfloat16 g_wt2[WT_TOTAL];
// per-(b,h) split planes of K (3) and V (2): [((b*4+h)*SL + j)*32 + e]
#define PL_ELEMS (BB*HH*SL*DKH)
__device__ __nv_bfloat16 g_k0[PL_ELEMS];
__device__ __nv_bfloat16 g_k1[PL_ELEMS];
__device__ __nv_bfloat16 g_k2[PL_ELEMS];
__device__ __nv_bfloat16 g_v0[PL_ELEMS];
__device__ __nv_bfloat16 g_v1[PL_ELEMS];
__device__ int g_idx[NTOK];
__device__ int g_nb[BB];
__device__ int g_npad[BB];
__device__ int g_cnt[2];

// ---------------- PTX helpers -------------------------------------------------
__device__ __forceinline__ uint32_t smem_u32(const void* p) {
    uint32_t a;
    asm("{ .reg .u64 t; cvta.to.shared.u64 t, %1; cvt.u32.u64 %0, t; }" : "=r"(a) : "l"(p));
    return a;
}
__device__ __forceinline__ void ldsm4(uint32_t* r, uint32_t addr) {
    asm volatile("ldmatrix.sync.aligned.m8n8.x4.shared.b16 {%0,%1,%2,%3}, [%4];"
        : "=r"(r[0]), "=r"(r[1]), "=r"(r[2]), "=r"(r[3]) : "r"(addr));
}
__device__ __forceinline__ void ldsm4t(uint32_t* r, uint32_t addr) {
    asm volatile("ldmatrix.sync.aligned.m8n8.x4.trans.shared.b16 {%0,%1,%2,%3}, [%4];"
        : "=r"(r[0]), "=r"(r[1]), "=r"(r[2]), "=r"(r[3]) : "r"(addr));
}
__device__ __forceinline__ void mma16816(float* d, const uint32_t* a, const uint32_t* b) {
    asm volatile("mma.sync.aligned.m16n8k16.row.col.f32.bf16.bf16.f32 "
        "{%0,%1,%2,%3}, {%4,%5,%6,%7}, {%8,%9}, {%0,%1,%2,%3};"
        : "+f"(d[0]), "+f"(d[1]), "+f"(d[2]), "+f"(d[3])
        : "r"(a[0]), "r"(a[1]), "r"(a[2]), "r"(a[3]), "r"(b[0]), "r"(b[1]));
}
// scalar RN 3-way split (setup kernels only)
__device__ __forceinline__ void split3(float x, uint16_t& h0, uint16_t& h1, uint16_t& h2) {
    __nv_bfloat16 b0 = __float2bfloat16(x);
    float r1 = x - __bfloat162float(b0);
    __nv_bfloat16 b1 = __float2bfloat16(r1);
    float r2 = r1 - __bfloat162float(b1);
    __nv_bfloat16 b2 = __float2bfloat16(r2);
    h0 = __bfloat16_as_ushort(b0);
    h1 = __bfloat16_as_ushort(b1);
    h2 = __bfloat16_as_ushort(b2);
}
// paired RN 3-way split (bit-identical to 2x split3 + pack)
__device__ __forceinline__ void split3x2(float a, float b,
                                         uint32_t& q0, uint32_t& q1, uint32_t& q2) {
    asm("cvt.rn.bf16x2.f32 %0, %1, %2;" : "=r"(q0) : "f"(b), "f"(a));
    float ra = a - __uint_as_float(q0 << 16);
    float rb = b - __uint_as_float(q0 & 0xFFFF0000u);
    asm("cvt.rn.bf16x2.f32 %0, %1, %2;" : "=r"(q1) : "f"(rb), "f"(ra));
    float ra2 = ra - __uint_as_float(q1 << 16);
    float rb2 = rb - __uint_as_float(q1 & 0xFFFF0000u);
    asm("cvt.rn.bf16x2.f32 %0, %1, %2;" : "=r"(q2) : "f"(rb2), "f"(ra2));
}
__device__ __forceinline__ void split2x2(float a, float b, uint32_t& q0, uint32_t& q1) {
    asm("cvt.rn.bf16x2.f32 %0, %1, %2;" : "=r"(q0) : "f"(b), "f"(a));
    float ra = a - __uint_as_float(q0 << 16);
    float rb = b - __uint_as_float(q0 & 0xFFFF0000u);
    asm("cvt.rn.bf16x2.f32 %0, %1, %2;" : "=r"(q1) : "f"(rb), "f"(ra));
}

// ---------------- mask dtype detection ---------------------------------------
__global__ void mask_reset_kernel() {
    if (threadIdx.x < 2) g_cnt[threadIdx.x] = 0;
}
__global__ void mask_scan_kernel(const unsigned int* __restrict__ w) {
    int i = blockIdx.x*256 + threadIdx.x;
    unsigned int v = w[i];
    if (v > 1u) atomicOr(&g_cnt[0], 1);
    if (v != 0u && v != 0x3F800000u) atomicOr(&g_cnt[1], 1);
}

// ---------------- stable compaction (dtype dispatch fused) -------------------
__global__ void compact_kernel(const void* __restrict__ p)
{
    int b = blockIdx.x, tid = threadIdx.x;
    __shared__ int sc[256];
    __shared__ int sbase;
    int mode = (g_cnt[0] == 0) ? 0 : (g_cnt[1] == 0) ? 1 : 2;
    if (tid == 0) sbase = 0;
    __syncthreads();
    for (int c = 0; c < SL; c += 256) {
        int l = c + tid;
        int m;
        if (mode == 0)      m = ((const int*)p)[b*SL + l] != 0;
        else if (mode == 1) m = ((const float*)p)[b*SL + l] != 0.0f;
        else                m = ((const unsigned char*)p)[b*SL + l] != 0;
        sc[tid] = m;
        __syncthreads();
#pragma unroll
        for (int s = 1; s < 256; s <<= 1) {
            int v = (tid >= s) ? sc[tid - s] : 0;
            __syncthreads();
            sc[tid] += v;
            __syncthreads();
        }
        int pos = sbase + sc[tid] - m;
        if (m) g_idx[b*SL + pos] = l;
        int tot = sc[255];
        __syncthreads();
        if (tid == 0) sbase += tot;
        __syncthreads();
    }
    if (tid == 0) { g_nb[b] = sbase; g_npad[b] = (sbase + 127) & ~127; }
}

// ---------------- embedding (compacted) --------------------------------------
__global__ void embed_kernel(const float* __restrict__ values, const float* __restrict__ times,
                             const int* __restrict__ vars,
                             const float* __restrict__ W1t, const float* __restrict__ b1t,
                             const float* __restrict__ W2t,
                             const float* __restrict__ W1v, const float* __restrict__ b1v,
                             const float* __restrict__ W2v,
                             const float* __restrict__ vtab)
{
    int tok = blockIdx.x;
    int b = tok >> 11, j = tok & 2047;
    int d = threadIdx.x;
    if (j >= g_npad[b]) return;
    if (j >= g_nb[b]) { g_x[(size_t)tok*DD + d] = 0.f; return; }
    int l = g_idx[tok];
    __shared__ float tt[INTD], vv[INTD];
    if (d < INTD) {
        float t = times[b*SL + l], v = values[b*SL + l];
        tt[d] = tanhf(t * W1t[d] + b1t[d]);
        vv[d] = tanhf(v * W1v[d] + b1v[d]);
    }
    __syncthreads();
    int var = vars[b*SL + l];
    float acc = vtab[var*DD + d];
#pragma unroll
    for (int i = 0; i < INTD; i++)
        acc += tt[i]*W2t[i*DD+d] + vv[i]*W2v[i*DD+d];
    g_x[(size_t)tok*DD + d] = acc;
}

// ---------------- weight repack: transpose + bf16 3-way split ----------------
__global__ void wrepack_kernel(const float* __restrict__ Wq, const float* __restrict__ Wk,
                               const float* __restrict__ Wv, const float* __restrict__ Wo,
                               const float* __restrict__ W1, const float* __restrict__ W2,
                               const float* __restrict__ Wf)
{
    int idx = blockIdx.x*256 + threadIdx.x;      // < WT_TOTAL
    float v;
    if (idx >= WF_OFF) {             // fusion Wf: [dout][din] transposed
        int rr = idx - WF_OFF;
        int n = rr >> 7, k = rr & 127;
        v = Wf[k*DD + n];
    } else {
        int layer = idx >> 17;
        int r = idx & (WT_LAYER-1);
        if (r < WT_WO) {                 // qkv: n = sel*128+h*32+e, k = d
            int n = r >> 7, k = r & 127;
            int sel = n >> 7;
            int he = n & 127, h = he >> 5, e = he & 31;
            const float* W = sel == 0 ? Wq : (sel == 1 ? Wk : Wv);
            v = W[layer*HH*DD*DKH + h*DD*DKH + k*DKH + e];
        } else if (r < WT_W1) {          // wo: [dout][din]
            int rr = r - WT_WO; int n = rr >> 7, k = rr & 127;
            v = Wo[layer*DD*DD + k*DD + n];
        } else if (r < WT_W2) {          // w1: [f][d]
            int rr = r - WT_W1; int n = rr >> 7, k = rr & 127;
            v = W1[layer*DD*DFF + k*DFF + n];
        } else {                         // w2: [d][f]
            int rr = r - WT_W2; int n = rr >> 8, k = rr & 255;
            v = W2[layer*DFF*DD + k*DD + n];
        }
    }
    uint16_t h0, h1, h2;
    split3(v, h0, h1, h2);
    g_wt0[idx] = __ushort_as_bfloat16(h0);
    g_wt1[idx] = __ushort_as_bfloat16(h1);
    g_wt2[idx] = __ushort_as_bfloat16(h2);
}

// ---------------- HMMA 3-way-split GEMM: C tile 128x128 ----------------------
// epi: 0 none | 1 +=C | 2 bias+gelu | 3 bias+ +=C | 4 bias+tanh | 5 qkv (q->C, k/v->split planes)
#define PLANE 10240                        // 128 rows * 40 cols * 2B (tgemm planes)
#define TG_SMEM (6*PLANE)

__global__ __launch_bounds__(256)
void tgemm_kernel(const float* __restrict__ A,
                  const __nv_bfloat16* __restrict__ B0,
                  const __nv_bfloat16* __restrict__ B1,
                  const __nv_bfloat16* __restrict__ B2,
                  const float* __restrict__ bias,
                  float* __restrict__ C, int N, int K, int epi)
{
    int bm = blockIdx.y * 128;
    if ((bm & 2047) >= g_npad[bm >> 11]) return;
    int bn = blockIdx.x * 128;

    extern __shared__ char smem[];
    uint16_t (*sA0)[40] = (uint16_t(*)[40])(smem);
    uint16_t (*sA1)[40] = (uint16_t(*)[40])(smem + PLANE);
    uint16_t (*sA2)[40] = (uint16_t(*)[40])(smem + 2*PLANE);
    uint16_t (*sB0)[40] = (uint16_t(*)[40])(smem + 3*PLANE);
    uint16_t (*sB1)[40] = (uint16_t(*)[40])(smem + 4*PLANE);
    uint16_t (*sB2)[40] = (uint16_t(*)[40])(smem + 5*PLANE);

    int tid = threadIdx.x, wid = tid >> 5, lane = tid & 31;
    int wm = (wid & 3) * 32, wn = (wid >> 2) * 64;

    float acc[2][8][4];
#pragma unroll
    for (int mi = 0; mi < 2; mi++)
#pragma unroll
        for (int ni = 0; ni < 8; ni++)
#pragma unroll
            for (int c = 0; c < 4; c++) acc[mi][ni][c] = 0.f;

    uint32_t bA0 = smem_u32(sA0), bA1 = smem_u32(sA1), bA2 = smem_u32(sA2);
    uint32_t bB0 = smem_u32(sB0), bB1 = smem_u32(sB1), bB2 = smem_u32(sB2);
    int rowA = lane & 15, colA8 = (lane >> 4) * 8;
    int rowB = ((lane >> 4) << 3) + (lane & 7), colB8 = ((lane >> 3) & 1) * 8;

    int arow = tid >> 3, ac4 = (tid & 7) * 4;
    float4 areg[4];
#pragma unroll
    for (int it = 0; it < 4; it++) {
        int row = arow + it*32;
        areg[it] = *(const float4*)(A + (size_t)(bm + row)*K + ac4);
    }

    for (int k0 = 0; k0 < K; k0 += 32) {
#pragma unroll
        for (int it = 0; it < 4; it++) {
            int row = arow + it*32;
            float4 a = areg[it];
            uint32_t q00, q01, q02, q10, q11, q12;
            split3x2(a.x, a.y, q00, q01, q02);
            split3x2(a.z, a.w, q10, q11, q12);
            *(uint2*)&sA0[row][ac4] = make_uint2(q00, q10);
            *(uint2*)&sA1[row][ac4] = make_uint2(q01, q11);
            *(uint2*)&sA2[row][ac4] = make_uint2(q02, q12);
        }
#pragma unroll
        for (int it = 0; it < 4; it++) {
            int row = arow + it*32;
            size_t goff = (size_t)(bn + row)*K + k0 + ac4;
            *(uint2*)&sB0[row][ac4] = *(const uint2*)(B0 + goff);
            *(uint2*)&sB1[row][ac4] = *(const uint2*)(B1 + goff);
            *(uint2*)&sB2[row][ac4] = *(const uint2*)(B2 + goff);
        }
        __syncthreads();

        if (k0 + 32 < K) {
#pragma unroll
            for (int it = 0; it < 4; it++) {
                int row = arow + it*32;
                areg[it] = *(const float4*)(A + (size_t)(bm + row)*K + k0 + 32 + ac4);
            }
        }

#pragma unroll
        for (int ks = 0; ks < 32; ks += 16) {
            uint32_t a0[2][4], a1[2][4], a2[2][4];
#pragma unroll
            for (int mi = 0; mi < 2; mi++) {
                uint32_t off = ((uint32_t)((wm + mi*16 + rowA)*40 + ks + colA8)) * 2;
                ldsm4(a0[mi], bA0 + off);
                ldsm4(a1[mi], bA1 + off);
                ldsm4(a2[mi], bA2 + off);
            }
#pragma unroll
            for (int pi = 0; pi < 4; pi++) {
                uint32_t off = ((uint32_t)((wn + pi*16 + rowB)*40 + ks + colB8)) * 2;
                uint32_t b0[4], b1[4], b2[4];
                ldsm4(b0, bB0 + off);
                ldsm4(b1, bB1 + off);
                ldsm4(b2, bB2 + off);
#pragma unroll
                for (int mi = 0; mi < 2; mi++)
#pragma unroll
                    for (int nj = 0; nj < 2; nj++) {
                        float* ac = acc[mi][pi*2 + nj];
                        const uint32_t* f0 = &b0[nj*2];
                        const uint32_t* f1 = &b1[nj*2];
                        const uint32_t* f2 = &b2[nj*2];
                        mma16816(ac, a0[mi], f0);
                        mma16816(ac, a0[mi], f1);
                        mma16816(ac, a1[mi], f0);
                        mma16816(ac, a0[mi], f2);
                        mma16816(ac, a1[mi], f1);
                        mma16816(ac, a2[mi], f0);
                    }
            }
        }
        __syncthreads();
    }

    int r0base = bm + wm + (lane >> 2);
    int cbase = wn + (lane & 3) * 2;
#pragma unroll
    for (int mi = 0; mi < 2; mi++) {
#pragma unroll
        for (int ni = 0; ni < 8; ni++) {
            int col = bn + cbase + ni*8;
#pragma unroll
            for (int half = 0; half < 2; half++) {
                int row = r0base + mi*16 + half*8;
                float v0 = acc[mi][ni][half*2], v1 = acc[mi][ni][half*2+1];
                if (epi == 5) {
                    if (col < 128) {
                        *(float2*)(C + (size_t)row*N + col) = make_float2(v0, v1);
                    } else {
                        int cc = col - 128;
                        int sel = cc >> 7;
                        int hh = (cc >> 5) & 3;
                        int e  = cc & 31;
                        int bb = row >> 11, jj = row & 2047;
                        size_t dst = ((size_t)(bb*4 + hh)*SL + jj)*32 + e;
                        if (sel == 0) {
                            uint32_t w0, w1, w2;
                            split3x2(v0, v1, w0, w1, w2);
                            *(uint32_t*)(g_k0 + dst) = w0;
                            *(uint32_t*)(g_k1 + dst) = w1;
                            *(uint32_t*)(g_k2 + dst) = w2;
                        } else {
                            uint32_t w0, w1;
                            split2x2(v0, v1, w0, w1);
                            *(uint32_t*)(g_v0 + dst) = w0;
                            *(uint32_t*)(g_v1 + dst) = w1;
                        }
                    }
                    continue;
                }
                float* Cp = C + (size_t)row*N + col;
                if (epi >= 2) {
                    v0 += bias[col]; v1 += bias[col+1];
                }
                if (epi == 2) {
                    v0 = 0.5f*v0*(1.f + erff(v0*0.7071067811865476f));
                    v1 = 0.5f*v1*(1.f + erff(v1*0.7071067811865476f));
                }
                if (epi == 4) {
                    v0 = tanhf(v0);
                    v1 = tanhf(v1);
                }
                if (epi == 1 || epi == 3) {
                    float2 o = *(const float2*)Cp;
                    v0 += o.x; v1 += o.y;
                }
                *(float2*)Cp = make_float2(v0, v1);
            }
        }
    }
}

// ---------------- HMMA flash attention ---------------------------------------
// block: 8 warps, 256 queries (two 128-q halves share each staged KV tile);
// key tiles of 64, cp.async double-buffered
#define KPLANE 5120                  // one [64][40] uint16 KV plane
#define QPLANE2 20480                // one [256][40] uint16 Q plane
#define FL_SQ   0
#define FL_BUF  (3*QPLANE2)          // 61440
#define FL_BUFSZ (5*KPLANE)          // 25600
#define FL_SMEM (FL_BUF + 2*FL_BUFSZ)  // 112640

__device__ __forceinline__ void stage_kv_async(uint32_t dstb, int bh, int k0, int tid)
{
#pragma unroll
    for (int it = 0; it < 5; it++) {
        int idx = tid + it*256;             // 1280 uint4
        int plane = idx >> 8;               // 0..4
        int r = (idx >> 2) & 63;
        int e8 = (idx & 3) * 8;
        const __nv_bfloat16* src =
            plane == 0 ? g_k0 : plane == 1 ? g_k1 : plane == 2 ? g_k2 :
            plane == 3 ? g_v0 : g_v1;
        const void* gptr = src + ((size_t)bh*SL + k0 + r)*32 + e8;
        uint32_t dst = dstb + plane*KPLANE + r*80 + e8*2;
        asm volatile("cp.async.cg.shared.global [%0], [%1], 16;"
                     :: "r"(dst), "l"(gptr) : "memory");
    }
    asm volatile("cp.async.commit_group;" ::: "memory");
}

__global__ __launch_bounds__(256)
void flash_kernel()
{
    extern __shared__ char fsm[];
    int bh = blockIdx.y;
    int b = bh >> 2, h = bh & 3;
    int n = g_nb[b];
    int q0 = blockIdx.x * 256;
    if (q0 >= n) return;

    int tid = threadIdx.x, wid = tid >> 5, lane = tid & 31;
    uint32_t sbase = smem_u32(fsm);
    int run1 = (q0 + 128 < n);               // second half active?

    // ---- stage Q (fp32 -> RN 3-plane split, paired cvt), 256 rows ----
#pragma unroll
    for (int it = 0; it < 8; it++) {
        int idx = tid + it*256;                 // 2048 float4-groups
        int row = idx >> 3, c4 = (idx & 7) * 4;
        float4 f = *(const float4*)(g_qkv + (size_t)(b*SL + q0 + row)*384 + h*32 + c4);
        uint32_t q00, q01, q02, q10, q11, q12;
        split3x2(f.x, f.y, q00, q01, q02);
        split3x2(f.z, f.w, q10, q11, q12);
        *(uint2*)(fsm + FL_SQ + 0*QPLANE2 + row*80 + c4*2) = make_uint2(q00, q10);
        *(uint2*)(fsm + FL_SQ + 1*QPLANE2 + row*80 + c4*2) = make_uint2(q01, q11);
        *(uint2*)(fsm + FL_SQ + 2*QPLANE2 + row*80 + c4*2) = make_uint2(q02, q12);
    }
    __syncthreads();

    float mx[2][2], ls[2][2], oa[2][4][4];
#pragma unroll
    for (int hf = 0; hf < 2; hf++) {
        mx[hf][0] = -INFINITY; mx[hf][1] = -INFINITY;
        ls[hf][0] = 0.f; ls[hf][1] = 0.f;
#pragma unroll
        for (int i = 0; i < 4; i++)
#pragma unroll
            for (int u = 0; u < 4; u++) oa[hf][i][u] = 0.f;
    }

    int rowA = lane & 15, colA8 = (lane >> 4) * 8;
    int rowB = ((lane >> 4) << 3) + (lane & 7), colB8 = ((lane >> 3) & 1) * 8;

    int nt = (n + 63) >> 6;
    uint32_t bufb[2] = { sbase + FL_BUF, sbase + FL_BUF + FL_BUFSZ };
    stage_kv_async(bufb[0], bh, 0, tid);
    int cur = 0;

    for (int t = 0; t < nt; t++) {
        int k0 = t*64;
        asm volatile("cp.async.wait_group 0;" ::: "memory");
        __syncthreads();
        if (t + 1 < nt) stage_kv_async(bufb[cur ^ 1], bh, k0 + 64, tid);
        uint32_t kb = bufb[cur];
        uint32_t vb = bufb[cur] + 3*KPLANE;

#pragma unroll
        for (int hf = 0; hf < 2; hf++) {
            if (hf == 1 && !run1) break;
            // Q fragments for this half (from smem; cheap vs KV restage)
            uint32_t qf[3][2][4];
#pragma unroll
            for (int p = 0; p < 3; p++)
#pragma unroll
                for (int ks = 0; ks < 2; ks++)
                    ldsm4(qf[p][ks], sbase + FL_SQ + p*QPLANE2 +
                          (hf*128 + wid*16 + rowA)*80 + (ks*16 + colA8)*2);

            // ---- S = Q K^T (6-product RN split) ----
            float sf[8][4];
#pragma unroll
            for (int j = 0; j < 8; j++)
#pragma unroll
                for (int u = 0; u < 4; u++) sf[j][u] = 0.f;

#pragma unroll
            for (int ks = 0; ks < 2; ks++) {
#pragma unroll
                for (int i = 0; i < 4; i++) {
                    uint32_t off0 = kb + (i*16 + rowB)*80 + (ks*16 + colB8)*2;
                    uint32_t kb0[4], kb1[4], kb2[4];
                    ldsm4(kb0, off0);
                    ldsm4(kb1, off0 + KPLANE);
                    ldsm4(kb2, off0 + 2*KPLANE);
#pragma unroll
                    for (int nj = 0; nj < 2; nj++) {
                        float* s = sf[i*2 + nj];
                        const uint32_t* f0 = &kb0[nj*2];
                        const uint32_t* f1 = &kb1[nj*2];
                        const uint32_t* f2 = &kb2[nj*2];
                        mma16816(s, qf[0][ks], f0);
                        mma16816(s, qf[0][ks], f1);
                        mma16816(s, qf[1][ks], f0);
                        mma16816(s, qf[0][ks], f2);
                        mma16816(s, qf[1][ks], f1);
                        mma16816(s, qf[2][ks], f0);
                    }
                }
            }

            // ---- tail masking (exact FMIN) ----
            if (k0 + 64 > n) {
                int cb = 2*(lane & 3);
#pragma unroll
                for (int j = 0; j < 8; j++) {
                    int c = k0 + 8*j + cb;
                    if (c >= n)     { sf[j][0] = FMIN_F; sf[j][2] = FMIN_F; }
                    if (c + 1 >= n) { sf[j][1] = FMIN_F; sf[j][3] = FMIN_F; }
                }
            }

            // ---- online softmax ----
#pragma unroll
            for (int rh = 0; rh < 2; rh++) {
                float tm = -INFINITY;
#pragma unroll
                for (int j = 0; j < 8; j++)
                    tm = fmaxf(tm, fmaxf(sf[j][rh*2], sf[j][rh*2+1]));
                tm = fmaxf(tm, __shfl_xor_sync(0xFFFFFFFFu, tm, 1));
                tm = fmaxf(tm, __shfl_xor_sync(0xFFFFFFFFu, tm, 2));
                float nm = fmaxf(mx[hf][rh], tm);
                float c = __expf(mx[hf][rh] - nm);
                mx[hf][rh] = nm;
                float ps = 0.f;
#pragma unroll
                for (int j = 0; j < 8; j++) {
                    float e0 = __expf(sf[j][rh*2]   - nm);
                    float e1 = __expf(sf[j][rh*2+1] - nm);
                    sf[j][rh*2] = e0; sf[j][rh*2+1] = e1;
                    ps += e0 + e1;
                }
                ls[hf][rh] = ls[hf][rh]*c + ps;
#pragma unroll
                for (int nf = 0; nf < 4; nf++) {
                    oa[hf][nf][rh*2]   *= c;
                    oa[hf][nf][rh*2+1] *= c;
                }
            }

            // ---- O += P V (P RN 3-plane paired split, V RN 2-plane, 5 products) ----
#pragma unroll
            for (int g = 0; g < 4; g++) {
                float* s0 = sf[2*g];
                float* s1 = sf[2*g+1];
                uint32_t ap0[4], ap1[4], ap2[4];
                split3x2(s0[0], s0[1], ap0[0], ap1[0], ap2[0]);
                split3x2(s0[2], s0[3], ap0[1], ap1[1], ap2[1]);
                split3x2(s1[0], s1[1], ap0[2], ap1[2], ap2[2]);
                split3x2(s1[2], s1[3], ap0[3], ap1[3], ap2[3]);
#pragma unroll
                for (int nb = 0; nb < 2; nb++) {
                    uint32_t v0r[4], v1r[4];
                    uint32_t voff = vb + (g*16 + (lane & 15))*80 + (nb*16 + (lane >> 4)*8)*2;
                    ldsm4t(v0r, voff);
                    ldsm4t(v1r, voff + KPLANE);
#pragma unroll
                    for (int nj = 0; nj < 2; nj++) {
                        int nf = nb*2 + nj;
                        mma16816(oa[hf][nf], ap0, &v0r[nj*2]);
                        mma16816(oa[hf][nf], ap0, &v1r[nj*2]);
                        mma16816(oa[hf][nf], ap1, &v0r[nj*2]);
                        mma16816(oa[hf][nf], ap1, &v1r[nj*2]);
                        mma16816(oa[hf][nf], ap2, &v0r[nj*2]);
                    }
                }
            }
        }
        cur ^= 1;
    }

    // ---- epilogue (both halves) ----
#pragma unroll
    for (int hf = 0; hf < 2; hf++) {
        if (hf == 1 && !run1) break;
        float inv[2];
#pragma unroll
        for (int rh = 0; rh < 2; rh++) {
            float l = ls[hf][rh];
            l += __shfl_xor_sync(0xFFFFFFFFu, l, 1);
            l += __shfl_xor_sync(0xFFFFFFFFu, l, 2);
            inv[rh] = 1.f / l;
        }
        int r0 = q0 + hf*128 + wid*16 + (lane >> 2);
        int cb = 2*(lane & 3);
#pragma unroll
        for (int nf = 0; nf < 4; nf++)
#pragma unroll
            for (int rh = 0; rh < 2; rh++) {
                int row = r0 + rh*8;
                float2 val = make_float2(oa[hf][nf][rh*2]*inv[rh], oa[hf][nf][rh*2+1]*inv[rh]);
                *(float2*)(g_o + (size_t)(b*SL + row)*DD + h*32 + 8*nf + cb) = val;
            }
    }
}

// ---------------- fusion reduce: att[tok] = tanh(xWf+bf) . uf ----------------
__global__ void fuse_reduce_kernel(const float* __restrict__ uf)
{
    int wid = threadIdx.x >> 5, lane = threadIdx.x & 31;
    int tok = blockIdx.x*8 + wid;
    int b = tok >> 11, j = tok & 2047;
    if (j >= g_nb[b]) return;
    const float* f = g_ff + (size_t)tok*DD;
    float acc = 0.f;
#pragma unroll
    for (int t = 0; t < 4; t++) {
        int d = lane + t*32;
        acc += f[d] * uf[d];
    }
    acc += __shfl_xor_sync(0xFFFFFFFFu, acc, 16);
    acc += __shfl_xor_sync(0xFFFFFFFFu, acc, 8);
    acc += __shfl_xor_sync(0xFFFFFFFFu, acc, 4);
    acc += __shfl_xor_sync(0xFFFFFFFFu, acc, 2);
    acc += __shfl_xor_sync(0xFFFFFFFFu, acc, 1);
    if (lane == 0) g_att[tok] = acc;
}

// ---------------- masked softmax pooling -------------------------------------
__global__ void pool_kernel()
{
    int b = blockIdx.x;
    int n = g_nb[b];
    int tid = threadIdx.x;
    __shared__ float w[SL];
    __shared__ float red[256];
    float mx = -INFINITY;
    for (int l = tid; l < n; l += 256) mx = fmaxf(mx, g_att[b*SL + l]);
    red[tid] = mx; __syncthreads();
    for (int s = 128; s > 0; s >>= 1) { if (tid < s) red[tid] = fmaxf(red[tid], red[tid+s]); __syncthreads(); }
    mx = red[0]; __syncthreads();
    float sum = 0.f;
    for (int l = tid; l < n; l += 256) { float e = __expf(g_att[b*SL+l] - mx); w[l] = e; sum += e; }
    red[tid] = sum; __syncthreads();
    for (int s = 128; s > 0; s >>= 1) { if (tid < s) red[tid] += red[tid+s]; __syncthreads(); }
    float inv = 1.f / red[0];
    __syncthreads();
    int d = tid & 127, half = tid >> 7;
    float acc = 0.f;
    for (int l = half; l < n; l += 2)
        acc += w[l]*g_x[((size_t)b*SL + l)*DD + d];
    red[tid] = acc; __syncthreads();
    if (tid < 128) g_ts[b*DD + tid] = (red[tid] + red[tid+128])*inv;
}

// ---------------- demographics MLP -------------------------------------------
__global__ void demo_kernel(const float* __restrict__ demo, const float* __restrict__ Wd1,
                            const float* __restrict__ bd1, const float* __restrict__ Wd2,
                            const float* __restrict__ bd2)
{
    int b = blockIdx.x;
    int tid = threadIdx.x;
    __shared__ float ds[DMG];
    __shared__ float hs[256];
    if (tid < DMG) ds[tid] = demo[b*DMG + tid];
    __syncthreads();
    float a = bd1[tid];
#pragma unroll
    for (int k = 0; k < DMG; k++) a += ds[k]*Wd1[k*256 + tid];
    hs[tid] = tanhf(a);
    __syncthreads();
    if (tid < DD) {
        float a2 = bd2[tid];
#pragma unroll 8
        for (int k = 0; k < 256; k++) a2 += hs[k]*Wd2[k*DD + tid];
        g_demo[b*DD + tid] = a2;
    }
}

// ---------------- head --------------------------------------------------------
__global__ void head_kernel(const float* __restrict__ Wh, const float* __restrict__ bh,
                            float* __restrict__ out)
{
    int b = blockIdx.x;
    int tid = threadIdx.x;
    __shared__ float es[256];
    es[tid] = (tid < 128) ? g_ts[b*DD + tid] : g_demo[b*DD + (tid - 128)];
    __syncthreads();
    if (tid < NF) {
        float acc = bh[tid];
#pragma unroll 8
        for (int k = 0; k < 256; k++) acc += es[k]*Wh[k*NF + tid];
        out[b*NF + tid] = acc;
    }
}

// ---------------- orchestration ------------------------------------------------
extern "C" void kernel_launch(void* const* d_in, const int* in_sizes, int n_in,
                              void* d_out, int out_size)
{
    const float* values = (const float*)d_in[0];
    const float* times  = (const float*)d_in[1];
    const int*   vars   = (const int*)d_in[2];
    const void*  maskraw = d_in[3];
    const float* demo   = (const float*)d_in[4];
    const float* W1t = (const float*)d_in[5];
    const float* b1t = (const float*)d_in[6];
    const float* W2t = (const float*)d_in[7];
    const float* W1v = (const float*)d_in[8];
    const float* b1v = (const float*)d_in[9];
    const float* W2v = (const float*)d_in[10];
    const float* vtab = (const float*)d_in[11];
    const float* Wq = (const float*)d_in[12];
    const float* Wk = (const float*)d_in[13];
    const float* Wv = (const float*)d_in[14];
    const float* Wo = (const float*)d_in[15];
    const float* W1 = (const float*)d_in[16];
    const float* b1 = (const float*)d_in[17];
    const float* W2 = (const float*)d_in[18];
    const float* b2 = (const float*)d_in[19];
    const float* Wf = (const float*)d_in[20];
    const float* bf = (const float*)d_in[21];
    const float* uf = (const float*)d_in[22];
    const float* Wd1 = (const float*)d_in[23];
    const float* bd1 = (const float*)d_in[24];
    const float* Wd2 = (const float*)d_in[25];
    const float* bd2 = (const float*)d_in[26];
    const float* Wh = (const float*)d_in[27];
    const float* bh = (const float*)d_in[28];
    float* out = (float*)d_out;

    float *xp, *qkvp, *op, *ffp;
    __nv_bfloat16 *w0p, *w1p, *w2p;
    cudaGetSymbolAddress((void**)&xp,   g_x);
    cudaGetSymbolAddress((void**)&qkvp, g_qkv);
    cudaGetSymbolAddress((void**)&op,   g_o);
    cudaGetSymbolAddress((void**)&ffp,  g_ff);
    cudaGetSymbolAddress((void**)&w0p,  g_wt0);
    cudaGetSymbolAddress((void**)&w1p,  g_wt1);
    cudaGetSymbolAddress((void**)&w2p,  g_wt2);

    cudaFuncSetAttribute(tgemm_kernel, cudaFuncAttributeMaxDynamicSharedMemorySize, TG_SMEM);
    cudaFuncSetAttribute(flash_kernel, cudaFuncAttributeMaxDynamicSharedMemorySize, FL_SMEM);

    mask_reset_kernel<<<1, 32>>>();
    mask_scan_kernel<<<NTOK/4/256, 256>>>((const unsigned int*)maskraw);
    compact_kernel<<<BB, 256>>>(maskraw);

    wrepack_kernel<<<WT_TOTAL/256, 256>>>(Wq, Wk, Wv, Wo, W1, W2, Wf);
    demo_kernel<<<BB, 256>>>(demo, Wd1, bd1, Wd2, bd2);
    embed_kernel<<<NTOK, 128>>>(values, times, vars, W1t, b1t, W2t, W1v, b1v, W2v, vtab);

    for (int i = 0; i < NLAY; i++) {
        const __nv_bfloat16* l0 = w0p + i*WT_LAYER;
        const __nv_bfloat16* l1 = w1p + i*WT_LAYER;
        const __nv_bfloat16* l2 = w2p + i*WT_LAYER;
        // QKV GEMM with fused K/V plane split (epi=5)
        tgemm_kernel<<<dim3(3, NTOK/128), 256, TG_SMEM>>>(xp, l0 + WT_QKV, l1 + WT_QKV, l2 + WT_QKV,
                                                          nullptr, qkvp, 384, 128, 5);
        flash_kernel<<<dim3(SL/256, BB*HH), 256, FL_SMEM>>>();
        tgemm_kernel<<<dim3(1, NTOK/128), 256, TG_SMEM>>>(op, l0 + WT_WO, l1 + WT_WO, l2 + WT_WO,
                                                          nullptr, xp, 128, 128, 1);
        tgemm_kernel<<<dim3(2, NTOK/128), 256, TG_SMEM>>>(xp, l0 + WT_W1, l1 + WT_W1, l2 + WT_W1,
                                                          b1 + i*DFF, ffp, 256, 128, 2);
        tgemm_kernel<<<dim3(1, NTOK/128), 256, TG_SMEM>>>(ffp, l0 + WT_W2, l1 + WT_W2, l2 + WT_W2,
                                                          b2 + i*DD, xp, 128, 256, 3);
    }

    // fusion attention: tanh(x Wf + bf) via split-GEMM, then dot with uf
    tgemm_kernel<<<dim3(1, NTOK/128), 256, TG_SMEM>>>(xp, w0p + WF_OFF, w1p + WF_OFF, w2p + WF_OFF,
                                                      bf, ffp, 128, 128, 4);
    fuse_reduce_kernel<<<NTOK/8, 256>>>(uf);
    pool_kernel<<<BB, 256>>>();
    head_kernel<<<BB, 256>>>(Wh, bh, out);
}

// round 17
// speedup vs baseline: 1.2297x; 1.0078x over previous
#include <cuda_runtime.h>
#include <cuda_bf16.h>
#include <math.h>
#include <stdint.h>

#define BB   16
#define SL   2048
#define DD   128
#define HH   4
#define NLAY 4
#define DKH  32
#define DFF  256
#define NF   129
#define DMG  16
#define INTD 11
#define NTOK (BB*SL)
#define FMIN_F (-3.402823466e38f)

// per-layer transposed bf16 weight planes: qkv[384x128] | wo[128x128] | w1[256x128] | w2[128x256]
#define WT_LAYER 131072
#define WT_QKV   0
#define WT_WO    49152
#define WT_W1    65536
#define WT_W2    98304
#define WF_OFF   (NLAY*WT_LAYER)          // Wf plane appended after layer weights
#define WT_TOTAL (WF_OFF + DD*DD)

// ---------------- scratch (device globals: allocation-free) ----------------
__device__ float g_x[NTOK*DD];
__device__ float g_qkv[NTOK*3*DD];
__device__ float g_o[NTOK*DD];
__device__ float g_ff[NTOK*DFF];
__device__ float g_demo[BB*DD];
__device__ float g_att[BB*SL];
__device__ float g_ts[BB*DD];
__device__ __nv_bfloat16 g_wt0[WT_TOTAL];
__device__ __nv_bfloat16 g_wt1[WT_TOTAL];
__device__ __nv_bfloat16 g_wt2[WT_TOTAL];
// per-(b,h) split planes of K (3) and V (2): [((b*4+h)*SL + j)*32 + e]
#define PL_ELEMS (BB*HH*SL*DKH)
__device__ __nv_bfloat16 g_k0[PL_ELEMS];
__device__ __nv_bfloat16 g_k1[PL_ELEMS];
__device__ __nv_bfloat16 g_k2[PL_ELEMS];
__device__ __nv_bfloat16 g_v0[PL_ELEMS];
__device__ __nv_bfloat16 g_v1[PL_ELEMS];
__device__ int g_idx[NTOK];
__device__ int g_nb[BB];
__device__ int g_npad[BB];
__device__ int g_cnt[2];

// ---------------- PTX helpers -------------------------------------------------
__device__ __forceinline__ uint32_t smem_u32(const void* p) {
    uint32_t a;
    asm("{ .reg .u64 t; cvta.to.shared.u64 t, %1; cvt.u32.u64 %0, t; }" : "=r"(a) : "l"(p));
    return a;
}
__device__ __forceinline__ void ldsm4(uint32_t* r, uint32_t addr) {
    asm volatile("ldmatrix.sync.aligned.m8n8.x4.shared.b16 {%0,%1,%2,%3}, [%4];"
        : "=r"(r[0]), "=r"(r[1]), "=r"(r[2]), "=r"(r[3]) : "r"(addr));
}
__device__ __forceinline__ void ldsm4t(uint32_t* r, uint32_t addr) {
    asm volatile("ldmatrix.sync.aligned.m8n8.x4.trans.shared.b16 {%0,%1,%2,%3}, [%4];"
        : "=r"(r[0]), "=r"(r[1]), "=r"(r[2]), "=r"(r[3]) : "r"(addr));
}
__device__ __forceinline__ void mma16816(float* d, const uint32_t* a, const uint32_t* b) {
    asm volatile("mma.sync.aligned.m16n8k16.row.col.f32.bf16.bf16.f32 "
        "{%0,%1,%2,%3}, {%4,%5,%6,%7}, {%8,%9}, {%0,%1,%2,%3};"
        : "+f"(d[0]), "+f"(d[1]), "+f"(d[2]), "+f"(d[3])
        : "r"(a[0]), "r"(a[1]), "r"(a[2]), "r"(a[3]), "r"(b[0]), "r"(b[1]));
}
// scalar RN 3-way split (setup kernels only)
__device__ __forceinline__ void split3(float x, uint16_t& h0, uint16_t& h1, uint16_t& h2) {
    __nv_bfloat16 b0 = __float2bfloat16(x);
    float r1 = x - __bfloat162float(b0);
    __nv_bfloat16 b1 = __float2bfloat16(r1);
    float r2 = r1 - __bfloat162float(b1);
    __nv_bfloat16 b2 = __float2bfloat16(r2);
    h0 = __bfloat16_as_ushort(b0);
    h1 = __bfloat16_as_ushort(b1);
    h2 = __bfloat16_as_ushort(b2);
}
// paired RN 3-way split (bit-identical to 2x split3 + pack)
__device__ __forceinline__ void split3x2(float a, float b,
                                         uint32_t& q0, uint32_t& q1, uint32_t& q2) {
    asm("cvt.rn.bf16x2.f32 %0, %1, %2;" : "=r"(q0) : "f"(b), "f"(a));
    float ra = a - __uint_as_float(q0 << 16);
    float rb = b - __uint_as_float(q0 & 0xFFFF0000u);
    asm("cvt.rn.bf16x2.f32 %0, %1, %2;" : "=r"(q1) : "f"(rb), "f"(ra));
    float ra2 = ra - __uint_as_float(q1 << 16);
    float rb2 = rb - __uint_as_float(q1 & 0xFFFF0000u);
    asm("cvt.rn.bf16x2.f32 %0, %1, %2;" : "=r"(q2) : "f"(rb2), "f"(ra2));
}
__device__ __forceinline__ void split2x2(float a, float b, uint32_t& q0, uint32_t& q1) {
    asm("cvt.rn.bf16x2.f32 %0, %1, %2;" : "=r"(q0) : "f"(b), "f"(a));
    float ra = a - __uint_as_float(q0 << 16);
    float rb = b - __uint_as_float(q0 & 0xFFFF0000u);
    asm("cvt.rn.bf16x2.f32 %0, %1, %2;" : "=r"(q1) : "f"(rb), "f"(ra));
}

// ---------------- mask dtype detection ---------------------------------------
__global__ void mask_reset_kernel() {
    if (threadIdx.x < 2) g_cnt[threadIdx.x] = 0;
}
__global__ void mask_scan_kernel(const unsigned int* __restrict__ w) {
    int i = blockIdx.x*256 + threadIdx.x;
    unsigned int v = w[i];
    if (v > 1u) atomicOr(&g_cnt[0], 1);
    if (v != 0u && v != 0x3F800000u) atomicOr(&g_cnt[1], 1);
}

// ---------------- stable compaction (dtype dispatch fused) -------------------
__global__ void compact_kernel(const void* __restrict__ p)
{
    int b = blockIdx.x, tid = threadIdx.x;
    __shared__ int sc[256];
    __shared__ int sbase;
    int mode = (g_cnt[0] == 0) ? 0 : (g_cnt[1] == 0) ? 1 : 2;
    if (tid == 0) sbase = 0;
    __syncthreads();
    for (int c = 0; c < SL; c += 256) {
        int l = c + tid;
        int m;
        if (mode == 0)      m = ((const int*)p)[b*SL + l] != 0;
        else if (mode == 1) m = ((const float*)p)[b*SL + l] != 0.0f;
        else                m = ((const unsigned char*)p)[b*SL + l] != 0;
        sc[tid] = m;
        __syncthreads();
#pragma unroll
        for (int s = 1; s < 256; s <<= 1) {
            int v = (tid >= s) ? sc[tid - s] : 0;
            __syncthreads();
            sc[tid] += v;
            __syncthreads();
        }
        int pos = sbase + sc[tid] - m;
        if (m) g_idx[b*SL + pos] = l;
        int tot = sc[255];
        __syncthreads();
        if (tid == 0) sbase += tot;
        __syncthreads();
    }
    if (tid == 0) { g_nb[b] = sbase; g_npad[b] = (sbase + 127) & ~127; }
}

// ---------------- embedding (compacted) --------------------------------------
__global__ void embed_kernel(const float* __restrict__ values, const float* __restrict__ times,
                             const int* __restrict__ vars,
                             const float* __restrict__ W1t, const float* __restrict__ b1t,
                             const float* __restrict__ W2t,
                             const float* __restrict__ W1v, const float* __restrict__ b1v,
                             const float* __restrict__ W2v,
                             const float* __restrict__ vtab)
{
    int tok = blockIdx.x;
    int b = tok >> 11, j = tok & 2047;
    int d = threadIdx.x;
    if (j >= g_npad[b]) return;
    if (j >= g_nb[b]) { g_x[(size_t)tok*DD + d] = 0.f; return; }
    int l = g_idx[tok];
    __shared__ float tt[INTD], vv[INTD];
    if (d < INTD) {
        float t = times[b*SL + l], v = values[b*SL + l];
        tt[d] = tanhf(t * W1t[d] + b1t[d]);
        vv[d] = tanhf(v * W1v[d] + b1v[d]);
    }
    __syncthreads();
    int var = vars[b*SL + l];
    float acc = vtab[var*DD + d];
#pragma unroll
    for (int i = 0; i < INTD; i++)
        acc += tt[i]*W2t[i*DD+d] + vv[i]*W2v[i*DD+d];
    g_x[(size_t)tok*DD + d] = acc;
}

// ---------------- weight repack: transpose + bf16 3-way split ----------------
__global__ void wrepack_kernel(const float* __restrict__ Wq, const float* __restrict__ Wk,
                               const float* __restrict__ Wv, const float* __restrict__ Wo,
                               const float* __restrict__ W1, const float* __restrict__ W2,
                               const float* __restrict__ Wf)
{
    int idx = blockIdx.x*256 + threadIdx.x;      // < WT_TOTAL
    float v;
    if (idx >= WF_OFF) {             // fusion Wf: [dout][din] transposed
        int rr = idx - WF_OFF;
        int n = rr >> 7, k = rr & 127;
        v = Wf[k*DD + n];
    } else {
        int layer = idx >> 17;
        int r = idx & (WT_LAYER-1);
        if (r < WT_WO) {                 // qkv: n = sel*128+h*32+e, k = d
            int n = r >> 7, k = r & 127;
            int sel = n >> 7;
            int he = n & 127, h = he >> 5, e = he & 31;
            const float* W = sel == 0 ? Wq : (sel == 1 ? Wk : Wv);
            v = W[layer*HH*DD*DKH + h*DD*DKH + k*DKH + e];
        } else if (r < WT_W1) {          // wo: [dout][din]
            int rr = r - WT_WO; int n = rr >> 7, k = rr & 127;
            v = Wo[layer*DD*DD + k*DD + n];
        } else if (r < WT_W2) {          // w1: [f][d]
            int rr = r - WT_W1; int n = rr >> 7, k = rr & 127;
            v = W1[layer*DD*DFF + k*DFF + n];
        } else {                         // w2: [d][f]
            int rr = r - WT_W2; int n = rr >> 8, k = rr & 255;
            v = W2[layer*DFF*DD + k*DD + n];
        }
    }
    uint16_t h0, h1, h2;
    split3(v, h0, h1, h2);
    g_wt0[idx] = __ushort_as_bfloat16(h0);
    g_wt1[idx] = __ushort_as_bfloat16(h1);
    g_wt2[idx] = __ushort_as_bfloat16(h2);
}

// ---------------- HMMA 3-way-split GEMM: C tile 128x128 ----------------------
// epi: 0 none | 1 +=C | 2 bias+gelu | 3 bias+ +=C
//    | 4 fusion: bias+tanh, dot with uf, row-reduce -> g_att (no C write)
//    | 5 qkv (q->C, k/v->split planes)
#define PLANE 10240                        // 128 rows * 40 cols * 2B (tgemm planes)
#define TG_SMEM (6*PLANE)

__global__ __launch_bounds__(256)
void tgemm_kernel(const float* __restrict__ A,
                  const __nv_bfloat16* __restrict__ B0,
                  const __nv_bfloat16* __restrict__ B1,
                  const __nv_bfloat16* __restrict__ B2,
                  const float* __restrict__ bias,
                  const float* __restrict__ uf,
                  float* __restrict__ C, int N, int K, int epi)
{
    int bm = blockIdx.y * 128;
    if ((bm & 2047) >= g_npad[bm >> 11]) return;
    int bn = blockIdx.x * 128;

    extern __shared__ char smem[];
    uint16_t (*sA0)[40] = (uint16_t(*)[40])(smem);
    uint16_t (*sA1)[40] = (uint16_t(*)[40])(smem + PLANE);
    uint16_t (*sA2)[40] = (uint16_t(*)[40])(smem + 2*PLANE);
    uint16_t (*sB0)[40] = (uint16_t(*)[40])(smem + 3*PLANE);
    uint16_t (*sB1)[40] = (uint16_t(*)[40])(smem + 4*PLANE);
    uint16_t (*sB2)[40] = (uint16_t(*)[40])(smem + 5*PLANE);

    int tid = threadIdx.x, wid = tid >> 5, lane = tid & 31;
    int wm = (wid & 3) * 32, wn = (wid >> 2) * 64;

    float acc[2][8][4];
#pragma unroll
    for (int mi = 0; mi < 2; mi++)
#pragma unroll
        for (int ni = 0; ni < 8; ni++)
#pragma unroll
            for (int c = 0; c < 4; c++) acc[mi][ni][c] = 0.f;

    uint32_t bA0 = smem_u32(sA0), bA1 = smem_u32(sA1), bA2 = smem_u32(sA2);
    uint32_t bB0 = smem_u32(sB0), bB1 = smem_u32(sB1), bB2 = smem_u32(sB2);
    int rowA = lane & 15, colA8 = (lane >> 4) * 8;
    int rowB = ((lane >> 4) << 3) + (lane & 7), colB8 = ((lane >> 3) & 1) * 8;

    int arow = tid >> 3, ac4 = (tid & 7) * 4;
    float4 areg[4];
#pragma unroll
    for (int it = 0; it < 4; it++) {
        int row = arow + it*32;
        areg[it] = *(const float4*)(A + (size_t)(bm + row)*K + ac4);
    }

    for (int k0 = 0; k0 < K; k0 += 32) {
#pragma unroll
        for (int it = 0; it < 4; it++) {
            int row = arow + it*32;
            float4 a = areg[it];
            uint32_t q00, q01, q02, q10, q11, q12;
            split3x2(a.x, a.y, q00, q01, q02);
            split3x2(a.z, a.w, q10, q11, q12);
            *(uint2*)&sA0[row][ac4] = make_uint2(q00, q10);
            *(uint2*)&sA1[row][ac4] = make_uint2(q01, q11);
            *(uint2*)&sA2[row][ac4] = make_uint2(q02, q12);
        }
#pragma unroll
        for (int it = 0; it < 4; it++) {
            int row = arow + it*32;
            size_t goff = (size_t)(bn + row)*K + k0 + ac4;
            *(uint2*)&sB0[row][ac4] = *(const uint2*)(B0 + goff);
            *(uint2*)&sB1[row][ac4] = *(const uint2*)(B1 + goff);
            *(uint2*)&sB2[row][ac4] = *(const uint2*)(B2 + goff);
        }
        __syncthreads();

        if (k0 + 32 < K) {
#pragma unroll
            for (int it = 0; it < 4; it++) {
                int row = arow + it*32;
                areg[it] = *(const float4*)(A + (size_t)(bm + row)*K + k0 + 32 + ac4);
            }
        }

#pragma unroll
        for (int ks = 0; ks < 32; ks += 16) {
            uint32_t a0[2][4], a1[2][4], a2[2][4];
#pragma unroll
            for (int mi = 0; mi < 2; mi++) {
                uint32_t off = ((uint32_t)((wm + mi*16 + rowA)*40 + ks + colA8)) * 2;
                ldsm4(a0[mi], bA0 + off);
                ldsm4(a1[mi], bA1 + off);
                ldsm4(a2[mi], bA2 + off);
            }
#pragma unroll
            for (int pi = 0; pi < 4; pi++) {
                uint32_t off = ((uint32_t)((wn + pi*16 + rowB)*40 + ks + colB8)) * 2;
                uint32_t b0[4], b1[4], b2[4];
                ldsm4(b0, bB0 + off);
                ldsm4(b1, bB1 + off);
                ldsm4(b2, bB2 + off);
#pragma unroll
                for (int mi = 0; mi < 2; mi++)
#pragma unroll
                    for (int nj = 0; nj < 2; nj++) {
                        float* ac = acc[mi][pi*2 + nj];
                        const uint32_t* f0 = &b0[nj*2];
                        const uint32_t* f1 = &b1[nj*2];
                        const uint32_t* f2 = &b2[nj*2];
                        mma16816(ac, a0[mi], f0);
                        mma16816(ac, a0[mi], f1);
                        mma16816(ac, a1[mi], f0);
                        mma16816(ac, a0[mi], f2);
                        mma16816(ac, a1[mi], f1);
                        mma16816(ac, a2[mi], f0);
                    }
            }
        }
        __syncthreads();
    }

    int r0base = bm + wm + (lane >> 2);
    int cbase = wn + (lane & 3) * 2;

    if (epi == 4) {
        // fusion: att[row] = sum_col tanh(v + bias[col]) * uf[col]
        float* sred = (float*)smem;          // staging smem is free now (post-sync)
#pragma unroll
        for (int mi = 0; mi < 2; mi++)
#pragma unroll
            for (int half = 0; half < 2; half++) {
                float part = 0.f;
#pragma unroll
                for (int ni = 0; ni < 8; ni++) {
                    int col = bn + cbase + ni*8;
                    float v0 = acc[mi][ni][half*2] + bias[col];
                    float v1 = acc[mi][ni][half*2+1] + bias[col+1];
                    part += tanhf(v0)*uf[col] + tanhf(v1)*uf[col+1];
                }
                part += __shfl_xor_sync(0xFFFFFFFFu, part, 1);
                part += __shfl_xor_sync(0xFFFFFFFFu, part, 2);
                if ((lane & 3) == 0) {
                    int r = wm + mi*16 + half*8 + (lane >> 2);
                    sred[(wid >> 2)*128 + r] = part;
                }
            }
        __syncthreads();
        if (tid < 128)
            g_att[bm + tid] = sred[tid] + sred[128 + tid];
        return;
    }

#pragma unroll
    for (int mi = 0; mi < 2; mi++) {
#pragma unroll
        for (int ni = 0; ni < 8; ni++) {
            int col = bn + cbase + ni*8;
#pragma unroll
            for (int half = 0; half < 2; half++) {
                int row = r0base + mi*16 + half*8;
                float v0 = acc[mi][ni][half*2], v1 = acc[mi][ni][half*2+1];
                if (epi == 5) {
                    if (col < 128) {
                        *(float2*)(C + (size_t)row*N + col) = make_float2(v0, v1);
                    } else {
                        int cc = col - 128;
                        int sel = cc >> 7;
                        int hh = (cc >> 5) & 3;
                        int e  = cc & 31;
                        int bb = row >> 11, jj = row & 2047;
                        size_t dst = ((size_t)(bb*4 + hh)*SL + jj)*32 + e;
                        if (sel == 0) {
                            uint32_t w0, w1, w2;
                            split3x2(v0, v1, w0, w1, w2);
                            *(uint32_t*)(g_k0 + dst) = w0;
                            *(uint32_t*)(g_k1 + dst) = w1;
                            *(uint32_t*)(g_k2 + dst) = w2;
                        } else {
                            uint32_t w0, w1;
                            split2x2(v0, v1, w0, w1);
                            *(uint32_t*)(g_v0 + dst) = w0;
                            *(uint32_t*)(g_v1 + dst) = w1;
                        }
                    }
                    continue;
                }
                float* Cp = C + (size_t)row*N + col;
                if (epi >= 2) {
                    v0 += bias[col]; v1 += bias[col+1];
                }
                if (epi == 2) {
                    v0 = 0.5f*v0*(1.f + erff(v0*0.7071067811865476f));
                    v1 = 0.5f*v1*(1.f + erff(v1*0.7071067811865476f));
                }
                if (epi == 1 || epi == 3) {
                    float2 o = *(const float2*)Cp;
                    v0 += o.x; v1 += o.y;
                }
                *(float2*)Cp = make_float2(v0, v1);
            }
        }
    }
}

// ---------------- HMMA flash attention ---------------------------------------
// block: 8 warps, 256 queries (two 128-q halves share each staged KV tile);
// key tiles of 64, cp.async double-buffered
#define KPLANE 5120                  // one [64][40] uint16 KV plane
#define QPLANE2 20480                // one [256][40] uint16 Q plane
#define FL_SQ   0
#define FL_BUF  (3*QPLANE2)          // 61440
#define FL_BUFSZ (5*KPLANE)          // 25600
#define FL_SMEM (FL_BUF + 2*FL_BUFSZ)  // 112640

__device__ __forceinline__ void stage_kv_async(uint32_t dstb, int bh, int k0, int tid)
{
#pragma unroll
    for (int it = 0; it < 5; it++) {
        int idx = tid + it*256;             // 1280 uint4
        int plane = idx >> 8;               // 0..4
        int r = (idx >> 2) & 63;
        int e8 = (idx & 3) * 8;
        const __nv_bfloat16* src =
            plane == 0 ? g_k0 : plane == 1 ? g_k1 : plane == 2 ? g_k2 :
            plane == 3 ? g_v0 : g_v1;
        const void* gptr = src + ((size_t)bh*SL + k0 + r)*32 + e8;
        uint32_t dst = dstb + plane*KPLANE + r*80 + e8*2;
        asm volatile("cp.async.cg.shared.global [%0], [%1], 16;"
                     :: "r"(dst), "l"(gptr) : "memory");
    }
    asm volatile("cp.async.commit_group;" ::: "memory");
}

__global__ __launch_bounds__(256)
void flash_kernel()
{
    extern __shared__ char fsm[];
    int bh = blockIdx.y;
    int b = bh >> 2, h = bh & 3;
    int n = g_nb[b];
    int q0 = blockIdx.x * 256;
    if (q0 >= n) return;

    int tid = threadIdx.x, wid = tid >> 5, lane = tid & 31;
    uint32_t sbase = smem_u32(fsm);
    int run1 = (q0 + 128 < n);               // second half active?

    // ---- stage Q (fp32 -> RN 3-plane split, paired cvt), 256 rows ----
#pragma unroll
    for (int it = 0; it < 8; it++) {
        int idx = tid + it*256;                 // 2048 float4-groups
        int row = idx >> 3, c4 = (idx & 7) * 4;
        float4 f = *(const float4*)(g_qkv + (size_t)(b*SL + q0 + row)*384 + h*32 + c4);
        uint32_t q00, q01, q02, q10, q11, q12;
        split3x2(f.x, f.y, q00, q01, q02);
        split3x2(f.z, f.w, q10, q11, q12);
        *(uint2*)(fsm + FL_SQ + 0*QPLANE2 + row*80 + c4*2) = make_uint2(q00, q10);
        *(uint2*)(fsm + FL_SQ + 1*QPLANE2 + row*80 + c4*2) = make_uint2(q01, q11);
        *(uint2*)(fsm + FL_SQ + 2*QPLANE2 + row*80 + c4*2) = make_uint2(q02, q12);
    }
    __syncthreads();

    float mx[2][2], ls[2][2], oa[2][4][4];
#pragma unroll
    for (int hf = 0; hf < 2; hf++) {
        mx[hf][0] = -INFINITY; mx[hf][1] = -INFINITY;
        ls[hf][0] = 0.f; ls[hf][1] = 0.f;
#pragma unroll
        for (int i = 0; i < 4; i++)
#pragma unroll
            for (int u = 0; u < 4; u++) oa[hf][i][u] = 0.f;
    }

    int rowA = lane & 15, colA8 = (lane >> 4) * 8;
    int rowB = ((lane >> 4) << 3) + (lane & 7), colB8 = ((lane >> 3) & 1) * 8;

    int nt = (n + 63) >> 6;
    uint32_t bufb[2] = { sbase + FL_BUF, sbase + FL_BUF + FL_BUFSZ };
    stage_kv_async(bufb[0], bh, 0, tid);
    int cur = 0;

    for (int t = 0; t < nt; t++) {
        int k0 = t*64;
        asm volatile("cp.async.wait_group 0;" ::: "memory");
        __syncthreads();
        if (t + 1 < nt) stage_kv_async(bufb[cur ^ 1], bh, k0 + 64, tid);
        uint32_t kb = bufb[cur];
        uint32_t vb = bufb[cur] + 3*KPLANE;

#pragma unroll
        for (int hf = 0; hf < 2; hf++) {
            if (hf == 1 && !run1) break;
            uint32_t qf[3][2][4];
#pragma unroll
            for (int p = 0; p < 3; p++)
#pragma unroll
                for (int ks = 0; ks < 2; ks++)
                    ldsm4(qf[p][ks], sbase + FL_SQ + p*QPLANE2 +
                          (hf*128 + wid*16 + rowA)*80 + (ks*16 + colA8)*2);

            // ---- S = Q K^T (6-product RN split) ----
            float sf[8][4];
#pragma unroll
            for (int j = 0; j < 8; j++)
#pragma unroll
                for (int u = 0; u < 4; u++) sf[j][u] = 0.f;

#pragma unroll
            for (int ks = 0; ks < 2; ks++) {
#pragma unroll
                for (int i = 0; i < 4; i++) {
                    uint32_t off0 = kb + (i*16 + rowB)*80 + (ks*16 + colB8)*2;
                    uint32_t kb0[4], kb1[4], kb2[4];
                    ldsm4(kb0, off0);
                    ldsm4(kb1, off0 + KPLANE);
                    ldsm4(kb2, off0 + 2*KPLANE);
#pragma unroll
                    for (int nj = 0; nj < 2; nj++) {
                        float* s = sf[i*2 + nj];
                        const uint32_t* f0 = &kb0[nj*2];
                        const uint32_t* f1 = &kb1[nj*2];
                        const uint32_t* f2 = &kb2[nj*2];
                        mma16816(s, qf[0][ks], f0);
                        mma16816(s, qf[0][ks], f1);
                        mma16816(s, qf[1][ks], f0);
                        mma16816(s, qf[0][ks], f2);
                        mma16816(s, qf[1][ks], f1);
                        mma16816(s, qf[2][ks], f0);
                    }
                }
            }

            // ---- tail masking (exact FMIN) ----
            if (k0 + 64 > n) {
                int cb = 2*(lane & 3);
#pragma unroll
                for (int j = 0; j < 8; j++) {
                    int c = k0 + 8*j + cb;
                    if (c >= n)     { sf[j][0] = FMIN_F; sf[j][2] = FMIN_F; }
                    if (c + 1 >= n) { sf[j][1] = FMIN_F; sf[j][3] = FMIN_F; }
                }
            }

            // ---- online softmax ----
#pragma unroll
            for (int rh = 0; rh < 2; rh++) {
                float tm = -INFINITY;
#pragma unroll
                for (int j = 0; j < 8; j++)
                    tm = fmaxf(tm, fmaxf(sf[j][rh*2], sf[j][rh*2+1]));
                tm = fmaxf(tm, __shfl_xor_sync(0xFFFFFFFFu, tm, 1));
                tm = fmaxf(tm, __shfl_xor_sync(0xFFFFFFFFu, tm, 2));
                float nm = fmaxf(mx[hf][rh], tm);
                float c = __expf(mx[hf][rh] - nm);
                mx[hf][rh] = nm;
                float ps = 0.f;
#pragma unroll
                for (int j = 0; j < 8; j++) {
                    float e0 = __expf(sf[j][rh*2]   - nm);
                    float e1 = __expf(sf[j][rh*2+1] - nm);
                    sf[j][rh*2] = e0; sf[j][rh*2+1] = e1;
                    ps += e0 + e1;
                }
                ls[hf][rh] = ls[hf][rh]*c + ps;
#pragma unroll
                for (int nf = 0; nf < 4; nf++) {
                    oa[hf][nf][rh*2]   *= c;
                    oa[hf][nf][rh*2+1] *= c;
                }
            }

            // ---- O += P V (P RN 3-plane paired split, V RN 2-plane, 5 products) ----
#pragma unroll
            for (int g = 0; g < 4; g++) {
                float* s0 = sf[2*g];
                float* s1 = sf[2*g+1];
                uint32_t ap0[4], ap1[4], ap2[4];
                split3x2(s0[0], s0[1], ap0[0], ap1[0], ap2[0]);
                split3x2(s0[2], s0[3], ap0[1], ap1[1], ap2[1]);
                split3x2(s1[0], s1[1], ap0[2], ap1[2], ap2[2]);
                split3x2(s1[2], s1[3], ap0[3], ap1[3], ap2[3]);
#pragma unroll
                for (int nb = 0; nb < 2; nb++) {
                    uint32_t v0r[4], v1r[4];
                    uint32_t voff = vb + (g*16 + (lane & 15))*80 + (nb*16 + (lane >> 4)*8)*2;
                    ldsm4t(v0r, voff);
                    ldsm4t(v1r, voff + KPLANE);
#pragma unroll
                    for (int nj = 0; nj < 2; nj++) {
                        int nf = nb*2 + nj;
                        mma16816(oa[hf][nf], ap0, &v0r[nj*2]);
                        mma16816(oa[hf][nf], ap0, &v1r[nj*2]);
                        mma16816(oa[hf][nf], ap1, &v0r[nj*2]);
                        mma16816(oa[hf][nf], ap1, &v1r[nj*2]);
                        mma16816(oa[hf][nf], ap2, &v0r[nj*2]);
                    }
                }
            }
        }
        cur ^= 1;
    }

    // ---- epilogue (both halves) ----
#pragma unroll
    for (int hf = 0; hf < 2; hf++) {
        if (hf == 1 && !run1) break;
        float inv[2];
#pragma unroll
        for (int rh = 0; rh < 2; rh++) {
            float l = ls[hf][rh];
            l += __shfl_xor_sync(0xFFFFFFFFu, l, 1);
            l += __shfl_xor_sync(0xFFFFFFFFu, l, 2);
            inv[rh] = 1.f / l;
        }
        int r0 = q0 + hf*128 + wid*16 + (lane >> 2);
        int cb = 2*(lane & 3);
#pragma unroll
        for (int nf = 0; nf < 4; nf++)
#pragma unroll
            for (int rh = 0; rh < 2; rh++) {
                int row = r0 + rh*8;
                float2 val = make_float2(oa[hf][nf][rh*2]*inv[rh], oa[hf][nf][rh*2+1]*inv[rh]);
                *(float2*)(g_o + (size_t)(b*SL + row)*DD + h*32 + 8*nf + cb) = val;
            }
    }
}

// ---------------- masked softmax pooling -------------------------------------
__global__ void pool_kernel()
{
    int b = blockIdx.x;
    int n = g_nb[b];
    int tid = threadIdx.x;
    __shared__ float w[SL];
    __shared__ float red[256];
    float mx = -INFINITY;
    for (int l = tid; l < n; l += 256) mx = fmaxf(mx, g_att[b*SL + l]);
    red[tid] = mx; __syncthreads();
    for (int s = 128; s > 0; s >>= 1) { if (tid < s) red[tid] = fmaxf(red[tid], red[tid+s]); __syncthreads(); }
    mx = red[0]; __syncthreads();
    float sum = 0.f;
    for (int l = tid; l < n; l += 256) { float e = __expf(g_att[b*SL+l] - mx); w[l] = e; sum += e; }
    red[tid] = sum; __syncthreads();
    for (int s = 128; s > 0; s >>= 1) { if (tid < s) red[tid] += red[tid+s]; __syncthreads(); }
    float inv = 1.f / red[0];
    __syncthreads();
    int d = tid & 127, half = tid >> 7;
    float acc = 0.f;
    for (int l = half; l < n; l += 2)
        acc += w[l]*g_x[((size_t)b*SL + l)*DD + d];
    red[tid] = acc; __syncthreads();
    if (tid < 128) g_ts[b*DD + tid] = (red[tid] + red[tid+128])*inv;
}

// ---------------- demographics MLP + head (merged) ---------------------------
__global__ void head_kernel(const float* __restrict__ demo,
                            const float* __restrict__ Wd1, const float* __restrict__ bd1,
                            const float* __restrict__ Wd2, const float* __restrict__ bd2,
                            const float* __restrict__ Wh, const float* __restrict__ bh,
                            float* __restrict__ out)
{
    int b = blockIdx.x;
    int tid = threadIdx.x;
    __shared__ float ds[DMG];
    __shared__ float hs[256];
    __shared__ float es[256];
    if (tid < DMG) ds[tid] = demo[b*DMG + tid];
    if (tid < 128) es[tid] = g_ts[b*DD + tid];
    __syncthreads();
    float a = bd1[tid];
#pragma unroll
    for (int k = 0; k < DMG; k++) a += ds[k]*Wd1[k*256 + tid];
    hs[tid] = tanhf(a);
    __syncthreads();
    if (tid < DD) {
        float a2 = bd2[tid];
#pragma unroll 8
        for (int k = 0; k < 256; k++) a2 += hs[k]*Wd2[k*DD + tid];
        es[128 + tid] = a2;
    }
    __syncthreads();
    if (tid < NF) {
        float acc = bh[tid];
#pragma unroll 8
        for (int k = 0; k < 256; k++) acc += es[k]*Wh[k*NF + tid];
        out[b*NF + tid] = acc;
    }
}

// ---------------- orchestration ------------------------------------------------
extern "C" void kernel_launch(void* const* d_in, const int* in_sizes, int n_in,
                              void* d_out, int out_size)
{
    const float* values = (const float*)d_in[0];
    const float* times  = (const float*)d_in[1];
    const int*   vars   = (const int*)d_in[2];
    const void*  maskraw = d_in[3];
    const float* demo   = (const float*)d_in[4];
    const float* W1t = (const float*)d_in[5];
    const float* b1t = (const float*)d_in[6];
    const float* W2t = (const float*)d_in[7];
    const float* W1v = (const float*)d_in[8];
    const float* b1v = (const float*)d_in[9];
    const float* W2v = (const float*)d_in[10];
    const float* vtab = (const float*)d_in[11];
    const float* Wq = (const float*)d_in[12];
    const float* Wk = (const float*)d_in[13];
    const float* Wv = (const float*)d_in[14];
    const float* Wo = (const float*)d_in[15];
    const float* W1 = (const float*)d_in[16];
    const float* b1 = (const float*)d_in[17];
    const float* W2 = (const float*)d_in[18];
    const float* b2 = (const float*)d_in[19];
    const float* Wf = (const float*)d_in[20];
    const float* bf = (const float*)d_in[21];
    const float* uf = (const float*)d_in[22];
    const float* Wd1 = (const float*)d_in[23];
    const float* bd1 = (const float*)d_in[24];
    const float* Wd2 = (const float*)d_in[25];
    const float* bd2 = (const float*)d_in[26];
    const float* Wh = (const float*)d_in[27];
    const float* bh = (const float*)d_in[28];
    float* out = (float*)d_out;

    float *xp, *qkvp, *op, *ffp;
    __nv_bfloat16 *w0p, *w1p, *w2p;
    cudaGetSymbolAddress((void**)&xp,   g_x);
    cudaGetSymbolAddress((void**)&qkvp, g_qkv);
    cudaGetSymbolAddress((void**)&op,   g_o);
    cudaGetSymbolAddress((void**)&ffp,  g_ff);
    cudaGetSymbolAddress((void**)&w0p,  g_wt0);
    cudaGetSymbolAddress((void**)&w1p,  g_wt1);
    cudaGetSymbolAddress((void**)&w2p,  g_wt2);

    cudaFuncSetAttribute(tgemm_kernel, cudaFuncAttributeMaxDynamicSharedMemorySize, TG_SMEM);
    cudaFuncSetAttribute(flash_kernel, cudaFuncAttributeMaxDynamicSharedMemorySize, FL_SMEM);

    mask_reset_kernel<<<1, 32>>>();
    mask_scan_kernel<<<NTOK/4/256, 256>>>((const unsigned int*)maskraw);
    compact_kernel<<<BB, 256>>>(maskraw);

    wrepack_kernel<<<WT_TOTAL/256, 256>>>(Wq, Wk, Wv, Wo, W1, W2, Wf);
    embed_kernel<<<NTOK, 128>>>(values, times, vars, W1t, b1t, W2t, W1v, b1v, W2v, vtab);

    for (int i = 0; i < NLAY; i++) {
        const __nv_bfloat16* l0 = w0p + i*WT_LAYER;
        const __nv_bfloat16* l1 = w1p + i*WT_LAYER;
        const __nv_bfloat16* l2 = w2p + i*WT_LAYER;
        // QKV GEMM with fused K/V plane split (epi=5)
        tgemm_kernel<<<dim3(3, NTOK/128), 256, TG_SMEM>>>(xp, l0 + WT_QKV, l1 + WT_QKV, l2 + WT_QKV,
                                                          nullptr, nullptr, qkvp, 384, 128, 5);
        flash_kernel<<<dim3(SL/256, BB*HH), 256, FL_SMEM>>>();
        tgemm_kernel<<<dim3(1, NTOK/128), 256, TG_SMEM>>>(op, l0 + WT_WO, l1 + WT_WO, l2 + WT_WO,
                                                          nullptr, nullptr, xp, 128, 128, 1);
        tgemm_kernel<<<dim3(2, NTOK/128), 256, TG_SMEM>>>(xp, l0 + WT_W1, l1 + WT_W1, l2 + WT_W1,
                                                          b1 + i*DFF, nullptr, ffp, 256, 128, 2);
        tgemm_kernel<<<dim3(1, NTOK/128), 256, TG_SMEM>>>(ffp, l0 + WT_W2, l1 + WT_W2, l2 + WT_W2,
                                                          b2 + i*DD, nullptr, xp, 128, 256, 3);
    }

    // fusion attention: tanh(x Wf + bf) . uf computed in the GEMM epilogue -> g_att
    tgemm_kernel<<<dim3(1, NTOK/128), 256, TG_SMEM>>>(xp, w0p + WF_OFF, w1p + WF_OFF, w2p + WF_OFF,
                                                      bf, uf, nullptr, 128, 128, 4);
    pool_kernel<<<BB, 256>>>();
    head_kernel<<<BB, 256>>>(demo, Wd1, bd1, Wd2, bd2, Wh, bh, out);
}